// round 4
// baseline (speedup 1.0000x reference)
#include <cuda_runtime.h>
#include <math.h>

// Problem constants
#define NT 768          // tokens
#define CD 768          // channels
#define CSD 384         // single_cond channels
#define CPD 128         // pair channels
#define HH 16           // heads
#define KDIM 48         // head dim
#define FD 1536         // ffn intermediate
#define LL 8            // layers
#define NC (768*768)
#define NN (768*768)    // pair rows

// ---------------- static device scratch (no allocations allowed) ----------------
__device__ float g_pl[LL*16*768*768];        // [L,H,Nq,Nk] pair logits, 302MB
__device__ float g_pmean[NN];
__device__ float g_prstd[NN];
__device__ float g_scmean[NT];
__device__ float g_scrstd[NT];
__device__ float g_sig_attn[LL*NC];
__device__ float g_skip_attn[LL*NC];
__device__ float g_az_attn[LL*NC];
__device__ float g_sig_ffw[LL*NC];
__device__ float g_skip_ffw[LL*NC];
__device__ float g_az_ffw[LL*NC];
__device__ float g_x[NC];
__device__ float g_q[NC];
__device__ float g_k[NC];
__device__ float g_v[NC];
__device__ float g_gate[NC];
__device__ float g_attn[NC];
__device__ float g_u[768*3072];
__device__ float g_c[768*1536];
__device__ float g_pw[128*128];

__device__ __forceinline__ float sigf(float x){ return 1.0f/(1.0f+__expf(-x)); }

// ---------------- block reduce helpers ----------------
__device__ __forceinline__ float warp_sum(float v){
    #pragma unroll
    for(int o=16;o;o>>=1) v += __shfl_xor_sync(0xffffffffu, v, o);
    return v;
}
__device__ __forceinline__ float warp_max(float v){
    #pragma unroll
    for(int o=16;o;o>>=1) v = fmaxf(v, __shfl_xor_sync(0xffffffffu, v, o));
    return v;
}
__device__ __forceinline__ float block_sum(float v, float* sred){
    int lane = threadIdx.x & 31, w = threadIdx.x >> 5;
    v = warp_sum(v);
    if(lane==0) sred[w] = v;
    __syncthreads();
    float r = 0.f;
    int nw = blockDim.x >> 5;
    if(threadIdx.x < 32){
        float t = (threadIdx.x < nw) ? sred[threadIdx.x] : 0.f;
        t = warp_sum(t);
        if(threadIdx.x==0) sred[0] = t;
    }
    __syncthreads();
    r = sred[0];
    __syncthreads();
    return r;
}
__device__ __forceinline__ float block_max(float v, float* sred){
    int lane = threadIdx.x & 31, w = threadIdx.x >> 5;
    v = warp_max(v);
    if(lane==0) sred[w] = v;
    __syncthreads();
    float r;
    int nw = blockDim.x >> 5;
    if(threadIdx.x < 32){
        float t = (threadIdx.x < nw) ? sred[threadIdx.x] : -1e30f;
        t = warp_max(t);
        if(threadIdx.x==0) sred[0] = t;
    }
    __syncthreads();
    r = sred[0];
    __syncthreads();
    return r;
}

// ---------------- row stats (mean, rstd) : one warp per row ----------------
__global__ void rowstats_kernel(const float* __restrict__ X, float* __restrict__ mean,
                                float* __restrict__ rstd, int rows, int cols){
    int row = blockIdx.x * (blockDim.x >> 5) + (threadIdx.x >> 5);
    if(row >= rows) return;
    int lane = threadIdx.x & 31;
    const float* x = X + (size_t)row * cols;
    float s = 0.f, sq = 0.f;
    for(int c = lane; c < cols; c += 32){ float v = x[c]; s += v; sq += v*v; }
    s = warp_sum(s); sq = warp_sum(sq);
    if(lane == 0){
        float m = s / cols;
        float var = sq / cols - m*m;
        if(var < 0.f) var = 0.f;
        mean[row] = m;
        rstd[row] = rsqrtf(var + 1e-5f);
    }
}

// ---------------- repack pair_w [NSB,CP,S,H] -> B[c][n], n = (sb*4+s)*16+h ----------------
__global__ void repack_pw_kernel(const float* __restrict__ pw, float* __restrict__ out){
    int idx = blockIdx.x * blockDim.x + threadIdx.x;
    if(idx >= 128*128) return;
    int c = idx >> 7, r = idx & 127;
    int sb = r >> 6, j = r & 63;               // j = s*16+h
    out[idx] = pw[sb*8192 + c*64 + j];
}

// ---------------- generic tiled SGEMM (64x64x16, 4x4 microtile) ----------------
// A: [M,K] row-major (optional per-row LN via amean/arstd, per-k scale via ascale,
//    elementwise multiplier amul [M,K])
// B: [K,N] row-major
// Epilogue: +bias[n], sigmoid, *egate[m,n], +=C (acc), or transposed write C[n*M+m]
__global__ void __launch_bounds__(256) gemm_kernel(
    const float* __restrict__ A, const float* __restrict__ B, float* __restrict__ C,
    int M, int N, int K,
    const float* __restrict__ amean, const float* __restrict__ arstd,
    const float* __restrict__ ascale, const float* __restrict__ amul,
    const float* __restrict__ bias, int do_sig,
    const float* __restrict__ egate, int do_acc, int do_transc)
{
    __shared__ float As[16][68];
    __shared__ float Bs[16][68];
    const int tid  = threadIdx.x;
    const int m0   = blockIdx.x * 64;
    const int n0   = blockIdx.y * 64;
    const int tm   = (tid & 15) * 4;
    const int tn   = (tid >> 4) * 4;
    const int arow = tid >> 2;
    const int akq  = (tid & 3) * 4;
    const int brow = tid >> 4;
    const int bnq  = (tid & 15) * 4;

    float am = 0.f, ar = 1.f;
    if(amean){ am = amean[m0 + arow]; ar = arstd[m0 + arow]; }

    float acc[4][4];
    #pragma unroll
    for(int i=0;i<4;i++)
        #pragma unroll
        for(int j=0;j<4;j++) acc[i][j] = 0.f;

    const float* Aptr = A + (size_t)(m0 + arow) * K;
    const float* Mptr = amul ? amul + (size_t)(m0 + arow) * K : (const float*)0;

    for(int k0 = 0; k0 < K; k0 += 16){
        float4 av = *(const float4*)(Aptr + k0 + akq);
        if(amean){ av.x=(av.x-am)*ar; av.y=(av.y-am)*ar; av.z=(av.z-am)*ar; av.w=(av.w-am)*ar; }
        if(ascale){ float4 s = *(const float4*)(ascale + k0 + akq);
                    av.x*=s.x; av.y*=s.y; av.z*=s.z; av.w*=s.w; }
        if(Mptr){ float4 mv = *(const float4*)(Mptr + k0 + akq);
                  av.x*=mv.x; av.y*=mv.y; av.z*=mv.z; av.w*=mv.w; }
        As[akq+0][arow]=av.x; As[akq+1][arow]=av.y; As[akq+2][arow]=av.z; As[akq+3][arow]=av.w;
        *(float4*)&Bs[brow][bnq] = *(const float4*)(B + (size_t)(k0 + brow) * N + n0 + bnq);
        __syncthreads();
        #pragma unroll
        for(int kk=0;kk<16;kk++){
            float4 a4 = *(const float4*)&As[kk][tm];
            float4 b4 = *(const float4*)&Bs[kk][tn];
            float a[4] = {a4.x, a4.y, a4.z, a4.w};
            float b[4] = {b4.x, b4.y, b4.z, b4.w};
            #pragma unroll
            for(int i=0;i<4;i++)
                #pragma unroll
                for(int j=0;j<4;j++) acc[i][j] += a[i]*b[j];
        }
        __syncthreads();
    }

    if(!do_transc){
        #pragma unroll
        for(int i=0;i<4;i++){
            int m = m0 + tm + i;
            int n = n0 + tn;
            float4 r = make_float4(acc[i][0], acc[i][1], acc[i][2], acc[i][3]);
            if(bias){ float4 bv = *(const float4*)(bias + n);
                      r.x+=bv.x; r.y+=bv.y; r.z+=bv.z; r.w+=bv.w; }
            if(do_sig){ r.x=sigf(r.x); r.y=sigf(r.y); r.z=sigf(r.z); r.w=sigf(r.w); }
            if(egate){ float4 g = *(const float4*)(egate + (size_t)m*N + n);
                       r.x*=g.x; r.y*=g.y; r.z*=g.z; r.w*=g.w; }
            float* cp = C + (size_t)m*N + n;
            if(do_acc){ float4 c0 = *(const float4*)cp;
                        r.x+=c0.x; r.y+=c0.y; r.z+=c0.z; r.w+=c0.w; }
            *(float4*)cp = r;
        }
    } else {
        #pragma unroll
        for(int j=0;j<4;j++){
            int n = n0 + tn + j;
            float4 r = make_float4(acc[0][j], acc[1][j], acc[2][j], acc[3][j]);
            *(float4*)(C + (size_t)n*M + m0 + tm) = r;
        }
    }
}

// ---------------- fused adaLN apply: x = sig * LN(a) + skip (row of 768) ----------------
__global__ void __launch_bounds__(256) adaln_apply_kernel(
    const float* __restrict__ a, const float* __restrict__ sig,
    const float* __restrict__ skip, float* __restrict__ x)
{
    __shared__ float sred[32];
    int row = blockIdx.x;
    const float* arow = a + (size_t)row * 768;
    int t = threadIdx.x;
    float v0 = arow[t], v1 = arow[t+256], v2 = arow[t+512];
    float s = block_sum(v0+v1+v2, sred);
    float m = s * (1.f/768.f);
    float d0 = v0-m, d1 = v1-m, d2 = v2-m;
    float var = block_sum(d0*d0 + d1*d1 + d2*d2, sred) * (1.f/768.f);
    float rs = rsqrtf(var + 1e-5f);
    size_t base = (size_t)row * 768 + t;
    x[base]      = sig[base]      * (d0*rs) + skip[base];
    x[base+256]  = sig[base+256]  * (d1*rs) + skip[base+256];
    x[base+512]  = sig[base+512]  * (d2*rs) + skip[base+512];
}

// ---------------- attention: block per (q, h) ----------------
__global__ void __launch_bounds__(256) attn_kernel(
    const float* __restrict__ Q, const float* __restrict__ Kx,
    const float* __restrict__ V, const float* __restrict__ pl,
    const float* __restrict__ mask, float* __restrict__ O)
{
    __shared__ float s_q[48];
    __shared__ float s_l[768];
    __shared__ float sred[32];
    __shared__ float s_part[4][48];
    int q = blockIdx.x, h = blockIdx.y;
    int t = threadIdx.x;
    if(t < 48) s_q[t] = Q[(size_t)q*768 + h*48 + t];
    __syncthreads();

    const float scale = rsqrtf(48.f);
    const float* plrow = pl + ((size_t)h*768 + q) * 768;
    const float4* q4 = (const float4*)s_q;

    for(int k = t; k < 768; k += 256){
        const float4* k4 = (const float4*)(Kx + (size_t)k*768 + h*48);
        float d = 0.f;
        #pragma unroll
        for(int j=0;j<12;j++){
            float4 a = q4[j], b = k4[j];
            d += a.x*b.x + a.y*b.y + a.z*b.z + a.w*b.w;
        }
        s_l[k] = d * scale + 1e9f * (mask[k] - 1.f) + plrow[k];
    }
    __syncthreads();

    float mx = -1e30f;
    for(int k = t; k < 768; k += 256) mx = fmaxf(mx, s_l[k]);
    float gm = block_max(mx, sred);

    float psum = 0.f;
    for(int k = t; k < 768; k += 256){
        float e = __expf(s_l[k] - gm);
        s_l[k] = e;
        psum += e;
    }
    float gs = block_sum(psum, sred);
    float inv = 1.f / gs;
    __syncthreads();

    if(t < 192){
        int d = t % 48, seg = t / 48;
        float acc = 0.f;
        int k0 = seg * 192;
        for(int k = k0; k < k0 + 192; k++)
            acc += s_l[k] * V[(size_t)k*768 + h*48 + d];
        s_part[seg][d] = acc;
    }
    __syncthreads();
    if(t < 48){
        float r = (s_part[0][t] + s_part[1][t] + s_part[2][t] + s_part[3][t]) * inv;
        O[(size_t)q*768 + h*48 + t] = r;
    }
}

// ---------------- GLU: c = swish(u[:, :F]) * u[:, F:] ----------------
__global__ void glu_kernel(const float* __restrict__ u, float* __restrict__ c){
    int i = blockIdx.x * blockDim.x + threadIdx.x;
    if(i >= 768*1536) return;
    int row = i / 1536, col = i % 1536;
    float a = u[(size_t)row*3072 + col];
    float b = u[(size_t)row*3072 + 1536 + col];
    c[i] = a * sigf(a) * b;
}

// ---------------- host-side GEMM launcher ----------------
static void gemm(const float* A, const float* B, float* C, int M, int N, int K,
                 const float* amean, const float* arstd, const float* ascale,
                 const float* amul, const float* bias, int sig,
                 const float* egate, int acc, int transc)
{
    dim3 g(M/64, N/64);
    gemm_kernel<<<g, 256>>>(A, B, C, M, N, K, amean, arstd, ascale, amul,
                            bias, sig, egate, acc, transc);
}

extern "C" void kernel_launch(void* const* d_in, const int* in_sizes, int n_in,
                              void* d_out, int out_size)
{
    const float* act   = (const float*)d_in[0];
    const float* mask  = (const float*)d_in[1];
    const float* sc    = (const float*)d_in[2];
    const float* pc    = (const float*)d_in[3];
    const float* a_cln = (const float*)d_in[4];
    const float* a_csw = (const float*)d_in[5];
    const float* a_csb = (const float*)d_in[6];
    const float* a_cbw = (const float*)d_in[7];
    const float* qw    = (const float*)d_in[8];
    const float* qb    = (const float*)d_in[9];
    const float* kw    = (const float*)d_in[10];
    const float* vw    = (const float*)d_in[11];
    const float* gw    = (const float*)d_in[12];
    const float* gb    = (const float*)d_in[13];
    const float* ow    = (const float*)d_in[14];
    const float* a_azw = (const float*)d_in[15];
    const float* a_azb = (const float*)d_in[16];
    const float* f_cln = (const float*)d_in[17];
    const float* f_csw = (const float*)d_in[18];
    const float* f_csb = (const float*)d_in[19];
    const float* f_cbw = (const float*)d_in[20];
    const float* t1    = (const float*)d_in[21];
    const float* t2    = (const float*)d_in[22];
    const float* f_azw = (const float*)d_in[23];
    const float* f_azb = (const float*)d_in[24];
    const float* plsc  = (const float*)d_in[25];
    const float* pw    = (const float*)d_in[26];
    float* out = (float*)d_out;

    float *pl, *pm, *pr, *scm, *scr;
    float *sA, *kA, *zA, *sF, *kF, *zF;
    float *xb, *qB, *kB, *vB, *gB, *atB, *uB, *cB, *pwB;
    cudaGetSymbolAddress((void**)&pl,  g_pl);
    cudaGetSymbolAddress((void**)&pm,  g_pmean);
    cudaGetSymbolAddress((void**)&pr,  g_prstd);
    cudaGetSymbolAddress((void**)&scm, g_scmean);
    cudaGetSymbolAddress((void**)&scr, g_scrstd);
    cudaGetSymbolAddress((void**)&sA,  g_sig_attn);
    cudaGetSymbolAddress((void**)&kA,  g_skip_attn);
    cudaGetSymbolAddress((void**)&zA,  g_az_attn);
    cudaGetSymbolAddress((void**)&sF,  g_sig_ffw);
    cudaGetSymbolAddress((void**)&kF,  g_skip_ffw);
    cudaGetSymbolAddress((void**)&zF,  g_az_ffw);
    cudaGetSymbolAddress((void**)&xb,  g_x);
    cudaGetSymbolAddress((void**)&qB,  g_q);
    cudaGetSymbolAddress((void**)&kB,  g_k);
    cudaGetSymbolAddress((void**)&vB,  g_v);
    cudaGetSymbolAddress((void**)&gB,  g_gate);
    cudaGetSymbolAddress((void**)&atB, g_attn);
    cudaGetSymbolAddress((void**)&uB,  g_u);
    cudaGetSymbolAddress((void**)&cB,  g_c);
    cudaGetSymbolAddress((void**)&pwB, g_pw);

    // act -> out (residual stream lives in d_out)
    cudaMemcpyAsync(out, act, (size_t)NC * sizeof(float), cudaMemcpyDeviceToDevice, 0);

    // row stats for LayerNorms folded into GEMM A-loads
    rowstats_kernel<<<(NT + 7) / 8, 256>>>(sc, scm, scr, NT, CSD);
    rowstats_kernel<<<(NN + 7) / 8, 256>>>(pc, pm, pr, NN, CPD);

    // pair logits: LN(pair_cond)*pair_ln_scale @ W  -> g_pl [L,H,Nq,Nk]
    repack_pw_kernel<<<64, 256>>>(pw, pwB);
    gemm(pc, pwB, pl, NN, 128, 128, pm, pr, plsc, 0, 0, 0, 0, 0, /*transc=*/1);

    // per-layer conditioning precompute (act-independent)
    for(int l = 0; l < LL; l++){
        gemm(sc, a_csw + (size_t)l*CSD*CD, sA + (size_t)l*NC, NT, CD, CSD,
             scm, scr, a_cln + l*CSD, 0, a_csb + l*CD, 1, 0, 0, 0);
        gemm(sc, a_cbw + (size_t)l*CSD*CD, kA + (size_t)l*NC, NT, CD, CSD,
             scm, scr, a_cln + l*CSD, 0, 0, 0, 0, 0, 0);
        gemm(sc, a_azw + (size_t)l*CSD*CD, zA + (size_t)l*NC, NT, CD, CSD,
             0, 0, 0, 0, a_azb + l*CD, 1, 0, 0, 0);
        gemm(sc, f_csw + (size_t)l*CSD*CD, sF + (size_t)l*NC, NT, CD, CSD,
             scm, scr, f_cln + l*CSD, 0, f_csb + l*CD, 1, 0, 0, 0);
        gemm(sc, f_cbw + (size_t)l*CSD*CD, kF + (size_t)l*NC, NT, CD, CSD,
             scm, scr, f_cln + l*CSD, 0, 0, 0, 0, 0, 0);
        gemm(sc, f_azw + (size_t)l*CSD*CD, zF + (size_t)l*NC, NT, CD, CSD,
             0, 0, 0, 0, f_azb + l*CD, 1, 0, 0, 0);
    }

    // transformer layers
    for(int l = 0; l < LL; l++){
        // x = sig_attn * LN(a) + skip_attn
        adaln_apply_kernel<<<NT, 256>>>(out, sA + (size_t)l*NC, kA + (size_t)l*NC, xb);

        // q,k,v,gate projections
        gemm(xb, qw + (size_t)l*NC, qB, NT, CD, CD, 0,0,0,0, qb + l*CD, 0, 0, 0, 0);
        gemm(xb, kw + (size_t)l*NC, kB, NT, CD, CD, 0,0,0,0, 0, 0, 0, 0, 0);
        gemm(xb, vw + (size_t)l*NC, vB, NT, CD, CD, 0,0,0,0, 0, 0, 0, 0, 0);
        gemm(xb, gw + (size_t)l*NC, gB, NT, CD, CD, 0,0,0,0, gb + l*CD, 1, 0, 0, 0);

        // softmax attention with pair-logit bias
        attn_kernel<<<dim3(NT, HH), 256>>>(qB, kB, vB, pl + (size_t)l*16*NC, mask, atB);

        // a += sig_az_attn * ((attn*gate) @ out_w)
        gemm(atB, ow + (size_t)l*NC, out, NT, CD, CD, 0,0,0, gB, 0, 0,
             zA + (size_t)l*NC, /*acc=*/1, 0);

        // x = sig_ffw * LN(a) + skip_ffw
        adaln_apply_kernel<<<NT, 256>>>(out, sF + (size_t)l*NC, kF + (size_t)l*NC, xb);

        // u = x @ t1 ; c = swish(u_lo) * u_hi
        gemm(xb, t1 + (size_t)l*CD*2*FD, uB, NT, 2*FD, CD, 0,0,0,0, 0, 0, 0, 0, 0);
        glu_kernel<<<(768*1536)/256, 256>>>(uB, cB);

        // a += sig_az_ffw * (c @ t2)
        gemm(cB, t2 + (size_t)l*FD*CD, out, NT, CD, FD, 0,0,0,0, 0, 0,
             zF + (size_t)l*NC, /*acc=*/1, 0);
    }
}

// round 6
// speedup vs baseline: 2.0414x; 2.0414x over previous
#include <cuda_runtime.h>
#include <math.h>
#include <stdint.h>

// Problem constants
#define NT 768          // tokens
#define CD 768          // channels
#define CSD 384         // single_cond channels
#define CPD 128         // pair channels
#define HH 16           // heads
#define KDIM 48         // head dim
#define FD 1536         // ffn intermediate
#define LL 8            // layers
#define NC (768*768)
#define NN (768*768)    // pair rows

// ---------------- static device scratch ----------------
__device__ float g_pl[LL*16*768*768];        // [L,H,Nq,Nk] pair logits, 302MB
__device__ float g_pmean[NN];
__device__ float g_prstd[NN];
__device__ float g_scmean[NT];
__device__ float g_scrstd[NT];
__device__ float g_sig_attn[LL*NC];
__device__ float g_skip_attn[LL*NC];
__device__ float g_az_attn[LL*NC];
__device__ float g_sig_ffw[LL*NC];
__device__ float g_skip_ffw[LL*NC];
__device__ float g_az_ffw[LL*NC];
__device__ float g_x[NC];
__device__ float g_q[NC];
__device__ float g_k[NC];
__device__ float g_v[NC];
__device__ float g_gate[NC];
__device__ float g_attn[NC];
__device__ float g_u[768*3072];
__device__ float g_c[768*1536];
__device__ float g_pw[128*128];

__device__ __forceinline__ float sigf(float x){ return 1.0f/(1.0f+__expf(-x)); }

__device__ __forceinline__ uint32_t f2tf32(float x){
    uint32_t r; asm("cvt.rna.tf32.f32 %0, %1;" : "=r"(r) : "f"(x)); return r;
}

__device__ __forceinline__ float warp_sum(float v){
    #pragma unroll
    for(int o=16;o;o>>=1) v += __shfl_xor_sync(0xffffffffu, v, o);
    return v;
}
__device__ __forceinline__ float warp_max(float v){
    #pragma unroll
    for(int o=16;o;o>>=1) v = fmaxf(v, __shfl_xor_sync(0xffffffffu, v, o));
    return v;
}

// ---------------- row stats (mean, rstd) : one warp per row ----------------
__global__ void rowstats_kernel(const float* __restrict__ X, float* __restrict__ mean,
                                float* __restrict__ rstd, int rows, int cols){
    int row = blockIdx.x * (blockDim.x >> 5) + (threadIdx.x >> 5);
    if(row >= rows) return;
    int lane = threadIdx.x & 31;
    const float* x = X + (size_t)row * cols;
    float s = 0.f, sq = 0.f;
    for(int c = lane; c < cols; c += 32){ float v = x[c]; s += v; sq += v*v; }
    s = warp_sum(s); sq = warp_sum(sq);
    if(lane == 0){
        float m = s / cols;
        float var = sq / cols - m*m;
        if(var < 0.f) var = 0.f;
        mean[row] = m;
        rstd[row] = rsqrtf(var + 1e-5f);
    }
}

// ---------------- repack pair_w [NSB,CP,S,H] -> B[c][n], n = (sb*4+s)*16+h ----------------
__global__ void repack_pw_kernel(const float* __restrict__ pw, float* __restrict__ out){
    int idx = blockIdx.x * blockDim.x + threadIdx.x;
    if(idx >= 128*128) return;
    int c = idx >> 7, r = idx & 127;
    int sb = r >> 6, j = r & 63;               // j = s*16+h
    out[idx] = pw[sb*8192 + c*64 + j];
}

// ================= TF32 tensor-core GEMM (64x64x32 tiles, m16n8k8 mma) =================
// A: [M,K] row-major with optional fused per-row LN (amean/arstd), per-k scale
// (ascale), elementwise multiplier amul [M,K].
// B: [K,N] row-major. Batched over blockIdx.z with strides sB/sC/sBias/sScale.
// Epilogue: +bias[n], sigmoid, *egate[m,n], +=C (acc), transposed write C[n*M+m].
__global__ void __launch_bounds__(256) gemm_tf32_kernel(
    const float* __restrict__ A, const float* __restrict__ B, float* __restrict__ C,
    int M, int N, int K,
    const float* __restrict__ amean, const float* __restrict__ arstd,
    const float* __restrict__ ascale, const float* __restrict__ amul,
    const float* __restrict__ bias, int do_sig,
    const float* __restrict__ egate, int do_acc, int do_transc,
    long sB, long sC, long sBias, long sScale)
{
    __shared__ uint32_t As[32][72];   // [k][m], stride 72 -> conflict-free frag loads
    __shared__ uint32_t Bs[32][72];   // [k][n]

    const int z = blockIdx.z;
    const float* Bp = B + (size_t)z * sB;
    float* Cp = C + (size_t)z * sC;
    const float* biasp  = bias   ? bias   + (size_t)z * sBias  : (const float*)0;
    const float* scalep = ascale ? ascale + (size_t)z * sScale : (const float*)0;

    const int tid  = threadIdx.x;
    const int m0   = blockIdx.x * 64;
    const int n0   = blockIdx.y * 64;
    const int warp = tid >> 5, lane = tid & 31;
    const int wm   = warp & 3, wn = warp >> 2;     // warp tile: 16m x 32n
    const int lr   = lane >> 2, lc = lane & 3;

    // A loader: thread covers row (tid&63), k block (tid>>6)*8
    const int arow = tid & 63;
    const int akb  = (tid >> 6) * 8;
    float am = 0.f, ar = 1.f;
    if(amean){ am = amean[m0 + arow]; ar = arstd[m0 + arow]; }
    const float* Aptr = A + (size_t)(m0 + arow) * K;
    const float* Mptr = amul ? amul + (size_t)(m0 + arow) * K : (const float*)0;

    // B loader: thread covers k rows (tid>>4) and (tid>>4)+16, n (tid&15)*4
    const int bkr = tid >> 4;
    const int bnb = (tid & 15) * 4;

    float acc[4][4];
    #pragma unroll
    for(int j=0;j<4;j++){ acc[j][0]=0.f; acc[j][1]=0.f; acc[j][2]=0.f; acc[j][3]=0.f; }

    for(int k0 = 0; k0 < K; k0 += 32){
        // ---- load A tile (with fused transforms) ----
        float av[8];
        *(float4*)&av[0] = *(const float4*)(Aptr + k0 + akb);
        *(float4*)&av[4] = *(const float4*)(Aptr + k0 + akb + 4);
        if(amean){
            #pragma unroll
            for(int i=0;i<8;i++) av[i] = (av[i] - am) * ar;
        }
        if(scalep){
            float sv[8];
            *(float4*)&sv[0] = *(const float4*)(scalep + k0 + akb);
            *(float4*)&sv[4] = *(const float4*)(scalep + k0 + akb + 4);
            #pragma unroll
            for(int i=0;i<8;i++) av[i] *= sv[i];
        }
        if(Mptr){
            float mv[8];
            *(float4*)&mv[0] = *(const float4*)(Mptr + k0 + akb);
            *(float4*)&mv[4] = *(const float4*)(Mptr + k0 + akb + 4);
            #pragma unroll
            for(int i=0;i<8;i++) av[i] *= mv[i];
        }
        #pragma unroll
        for(int i=0;i<8;i++) As[akb + i][arow] = f2tf32(av[i]);

        // ---- load B tile ----
        {
            float4 b0 = *(const float4*)(Bp + (size_t)(k0 + bkr) * N + n0 + bnb);
            float4 b1 = *(const float4*)(Bp + (size_t)(k0 + bkr + 16) * N + n0 + bnb);
            uint32_t* d0 = &Bs[bkr][bnb];
            uint32_t* d1 = &Bs[bkr + 16][bnb];
            d0[0]=f2tf32(b0.x); d0[1]=f2tf32(b0.y); d0[2]=f2tf32(b0.z); d0[3]=f2tf32(b0.w);
            d1[0]=f2tf32(b1.x); d1[1]=f2tf32(b1.y); d1[2]=f2tf32(b1.z); d1[3]=f2tf32(b1.w);
        }
        __syncthreads();

        #pragma unroll
        for(int ks = 0; ks < 4; ks++){
            const int kk = ks * 8;
            uint32_t a[4];
            a[0] = As[kk + lc    ][wm*16 + lr    ];
            a[1] = As[kk + lc    ][wm*16 + lr + 8];
            a[2] = As[kk + lc + 4][wm*16 + lr    ];
            a[3] = As[kk + lc + 4][wm*16 + lr + 8];
            #pragma unroll
            for(int j = 0; j < 4; j++){
                uint32_t b0 = Bs[kk + lc    ][wn*32 + j*8 + lr];
                uint32_t b1 = Bs[kk + lc + 4][wn*32 + j*8 + lr];
                asm volatile(
                    "mma.sync.aligned.m16n8k8.row.col.f32.tf32.tf32.f32 "
                    "{%0,%1,%2,%3}, {%4,%5,%6,%7}, {%8,%9}, {%0,%1,%2,%3};"
                    : "+f"(acc[j][0]), "+f"(acc[j][1]), "+f"(acc[j][2]), "+f"(acc[j][3])
                    : "r"(a[0]), "r"(a[1]), "r"(a[2]), "r"(a[3]), "r"(b0), "r"(b1));
            }
        }
        __syncthreads();
    }

    // ---- epilogue ----
    #pragma unroll
    for(int j = 0; j < 4; j++){
        int cc = n0 + wn*32 + j*8 + lc*2;
        #pragma unroll
        for(int h = 0; h < 2; h++){
            int rr = m0 + wm*16 + lr + h*8;
            float2 r = make_float2(acc[j][2*h], acc[j][2*h+1]);
            if(biasp){ float2 bv = *(const float2*)(biasp + cc); r.x += bv.x; r.y += bv.y; }
            if(do_sig){ r.x = sigf(r.x); r.y = sigf(r.y); }
            if(egate){ float2 g = *(const float2*)(egate + (size_t)rr*N + cc);
                       r.x *= g.x; r.y *= g.y; }
            if(!do_transc){
                float* cp = Cp + (size_t)rr*N + cc;
                if(do_acc){ float2 c0 = *(const float2*)cp; r.x += c0.x; r.y += c0.y; }
                *(float2*)cp = r;
            } else {
                Cp[(size_t)cc    *M + rr] = r.x;
                Cp[(size_t)(cc+1)*M + rr] = r.y;
            }
        }
    }
}

// ---------------- fused adaLN apply: x = sig * LN(a) + skip ----------------
__global__ void __launch_bounds__(256) adaln_apply_kernel(
    const float* __restrict__ a, const float* __restrict__ sig,
    const float* __restrict__ skip, float* __restrict__ x)
{
    __shared__ float sred[32];
    int row = blockIdx.x;
    const float* arow = a + (size_t)row * 768;
    int t = threadIdx.x, lane = t & 31, w = t >> 5;
    float v0 = arow[t], v1 = arow[t+256], v2 = arow[t+512];
    float s = warp_sum(v0+v1+v2);
    if(lane==0) sred[w] = s;
    __syncthreads();
    if(t < 32){ float q = (t < 8) ? sred[t] : 0.f; sred[t] = warp_sum(q); }
    __syncthreads();
    float m = sred[0] * (1.f/768.f);
    __syncthreads();
    float d0 = v0-m, d1 = v1-m, d2 = v2-m;
    float vv = warp_sum(d0*d0 + d1*d1 + d2*d2);
    if(lane==0) sred[w] = vv;
    __syncthreads();
    if(t < 32){ float q = (t < 8) ? sred[t] : 0.f; sred[t] = warp_sum(q); }
    __syncthreads();
    float rs = rsqrtf(sred[0] * (1.f/768.f) + 1e-5f);
    size_t base = (size_t)row * 768 + t;
    x[base]      = sig[base]      * (d0*rs) + skip[base];
    x[base+256]  = sig[base+256]  * (d1*rs) + skip[base+256];
    x[base+512]  = sig[base+512]  * (d2*rs) + skip[base+512];
}

// ================= attention v2: block per (32-query tile, head) =================
// smem: sQ[32][49], sKV[128][49], sP[32][772], sSum[32]  (~127KB dynamic)
#define SP_STRIDE 772
__global__ void __launch_bounds__(256) attn2_kernel(
    const float* __restrict__ Q, const float* __restrict__ Kx,
    const float* __restrict__ V, const float* __restrict__ pl,
    const float* __restrict__ mask, float* __restrict__ O)
{
    extern __shared__ float sm[];
    float* sQ   = sm;                          // 32*49
    float* sKV  = sQ + 32*49;                  // 128*49
    float* sP   = sKV + 128*49;                // 32*772
    float* sSum = sP + 32*SP_STRIDE;           // 32

    const int qt = blockIdx.x, h = blockIdx.y;
    const int q0 = qt * 32;
    const int tid = threadIdx.x;
    const float scale = rsqrtf(48.f);

    // load Q tile
    for(int i = tid; i < 32*48; i += 256){
        int q = i / 48, d = i % 48;
        sQ[q*49 + d] = Q[(size_t)(q0+q)*768 + h*48 + d];
    }

    // ---------- pass 1: S = QK^T*scale + pl + maskbias ----------
    const int qa = (tid & 7) * 4;
    const int ka = (tid >> 3) * 4;
    for(int kt = 0; kt < 6; kt++){
        __syncthreads();
        for(int i = tid; i < 128*48; i += 256){
            int k = i / 48, d = i % 48;
            sKV[k*49 + d] = Kx[(size_t)(kt*128 + k)*768 + h*48 + d];
        }
        __syncthreads();
        float s[4][4];
        #pragma unroll
        for(int i=0;i<4;i++){ s[i][0]=0.f; s[i][1]=0.f; s[i][2]=0.f; s[i][3]=0.f; }
        #pragma unroll 4
        for(int d = 0; d < 48; d++){
            float qv[4], kv[4];
            #pragma unroll
            for(int i=0;i<4;i++) qv[i] = sQ[(qa+i)*49 + d];
            #pragma unroll
            for(int j=0;j<4;j++) kv[j] = sKV[(ka+j)*49 + d];
            #pragma unroll
            for(int i=0;i<4;i++)
                #pragma unroll
                for(int j=0;j<4;j++) s[i][j] += qv[i]*kv[j];
        }
        int kg = kt*128 + ka;
        float4 mk = *(const float4*)(mask + kg);
        float bb[4] = {1e9f*(mk.x-1.f), 1e9f*(mk.y-1.f), 1e9f*(mk.z-1.f), 1e9f*(mk.w-1.f)};
        #pragma unroll
        for(int i=0;i<4;i++){
            float4 plv = *(const float4*)(pl + ((size_t)h*768 + q0+qa+i)*768 + kg);
            float* prow = sP + (qa+i)*SP_STRIDE + kg;
            prow[0] = s[i][0]*scale + plv.x + bb[0];
            prow[1] = s[i][1]*scale + plv.y + bb[1];
            prow[2] = s[i][2]*scale + plv.z + bb[2];
            prow[3] = s[i][3]*scale + plv.w + bb[3];
        }
    }
    __syncthreads();

    // ---------- softmax per row (warp handles 4 rows) ----------
    {
        int warp = tid >> 5, lane = tid & 31;
        for(int r = warp*4; r < warp*4 + 4; r++){
            float* row = sP + r*SP_STRIDE;
            float mx = -1e30f;
            for(int k = lane; k < 768; k += 32) mx = fmaxf(mx, row[k]);
            mx = warp_max(mx);
            float sum = 0.f;
            for(int k = lane; k < 768; k += 32){
                float e = __expf(row[k] - mx);
                row[k] = e;
                sum += e;
            }
            sum = warp_sum(sum);
            if(lane == 0) sSum[r] = sum;
        }
    }
    __syncthreads();

    // ---------- pass 2: O = P @ V (k split over 2 groups) ----------
    const int g  = tid >> 7;              // 0,1
    const int tt = tid & 127;
    const int q  = (tt >> 3) * 2;
    const int d0 = (tt & 7) * 6;
    float oa[2][6];
    #pragma unroll
    for(int j=0;j<6;j++){ oa[0][j]=0.f; oa[1][j]=0.f; }

    for(int kt = 0; kt < 6; kt++){
        __syncthreads();
        for(int i = tid; i < 128*48; i += 256){
            int k = i / 48, d = i % 48;
            sKV[k*49 + d] = V[(size_t)(kt*128 + k)*768 + h*48 + d];
        }
        __syncthreads();
        const int kbase = kt*128 + g*64;
        const float* p0r = sP + q*SP_STRIDE + kbase;
        const float* p1r = sP + (q+1)*SP_STRIDE + kbase;
        const float* vb  = sKV + (g*64)*49 + d0;
        #pragma unroll 4
        for(int kk = 0; kk < 64; kk++){
            float p0 = p0r[kk], p1 = p1r[kk];
            const float* vr = vb + kk*49;
            #pragma unroll
            for(int j=0;j<6;j++){
                float v = vr[j];
                oa[0][j] += p0 * v;
                oa[1][j] += p1 * v;
            }
        }
    }
    __syncthreads();
    // combine the two k-groups (reuse sP as scratch)
    if(g == 1){
        #pragma unroll
        for(int j=0;j<6;j++){ sP[tt*12 + j] = oa[0][j]; sP[tt*12 + 6 + j] = oa[1][j]; }
    }
    __syncthreads();
    if(g == 0){
        float inv0 = 1.f / sSum[q], inv1 = 1.f / sSum[q+1];
        #pragma unroll
        for(int j=0;j<6;j++){
            float o0 = (oa[0][j] + sP[tt*12 + j])     * inv0;
            float o1 = (oa[1][j] + sP[tt*12 + 6 + j]) * inv1;
            O[(size_t)(q0+q  )*768 + h*48 + d0 + j] = o0;
            O[(size_t)(q0+q+1)*768 + h*48 + d0 + j] = o1;
        }
    }
}

// ---------------- GLU: c = swish(u[:, :F]) * u[:, F:] ----------------
__global__ void glu_kernel(const float* __restrict__ u, float* __restrict__ c){
    int i = blockIdx.x * blockDim.x + threadIdx.x;
    if(i >= 768*1536) return;
    int row = i / 1536, col = i % 1536;
    float a = u[(size_t)row*3072 + col];
    float b = u[(size_t)row*3072 + 1536 + col];
    c[i] = a * sigf(a) * b;
}

// ---------------- host-side GEMM launcher ----------------
static void gemmT(const float* A, const float* B, float* C, int M, int N, int K,
                  const float* amean, const float* arstd, const float* ascale,
                  const float* amul, const float* bias, int sig,
                  const float* egate, int acc, int transc,
                  int batch, long sB, long sC, long sBias, long sScale)
{
    dim3 g(M/64, N/64, batch);
    gemm_tf32_kernel<<<g, 256>>>(A, B, C, M, N, K, amean, arstd, ascale, amul,
                                 bias, sig, egate, acc, transc,
                                 sB, sC, sBias, sScale);
}

extern "C" void kernel_launch(void* const* d_in, const int* in_sizes, int n_in,
                              void* d_out, int out_size)
{
    const float* act   = (const float*)d_in[0];
    const float* mask  = (const float*)d_in[1];
    const float* sc    = (const float*)d_in[2];
    const float* pc    = (const float*)d_in[3];
    const float* a_cln = (const float*)d_in[4];
    const float* a_csw = (const float*)d_in[5];
    const float* a_csb = (const float*)d_in[6];
    const float* a_cbw = (const float*)d_in[7];
    const float* qw    = (const float*)d_in[8];
    const float* qb    = (const float*)d_in[9];
    const float* kw    = (const float*)d_in[10];
    const float* vw    = (const float*)d_in[11];
    const float* gw    = (const float*)d_in[12];
    const float* gb    = (const float*)d_in[13];
    const float* ow    = (const float*)d_in[14];
    const float* a_azw = (const float*)d_in[15];
    const float* a_azb = (const float*)d_in[16];
    const float* f_cln = (const float*)d_in[17];
    const float* f_csw = (const float*)d_in[18];
    const float* f_csb = (const float*)d_in[19];
    const float* f_cbw = (const float*)d_in[20];
    const float* t1    = (const float*)d_in[21];
    const float* t2    = (const float*)d_in[22];
    const float* f_azw = (const float*)d_in[23];
    const float* f_azb = (const float*)d_in[24];
    const float* plsc  = (const float*)d_in[25];
    const float* pw    = (const float*)d_in[26];
    float* out = (float*)d_out;

    float *pl, *pm, *pr, *scm, *scr;
    float *sA, *kA, *zA, *sF, *kF, *zF;
    float *xb, *qB, *kB, *vB, *gB, *atB, *uB, *cB, *pwB;
    cudaGetSymbolAddress((void**)&pl,  g_pl);
    cudaGetSymbolAddress((void**)&pm,  g_pmean);
    cudaGetSymbolAddress((void**)&pr,  g_prstd);
    cudaGetSymbolAddress((void**)&scm, g_scmean);
    cudaGetSymbolAddress((void**)&scr, g_scrstd);
    cudaGetSymbolAddress((void**)&sA,  g_sig_attn);
    cudaGetSymbolAddress((void**)&kA,  g_skip_attn);
    cudaGetSymbolAddress((void**)&zA,  g_az_attn);
    cudaGetSymbolAddress((void**)&sF,  g_sig_ffw);
    cudaGetSymbolAddress((void**)&kF,  g_skip_ffw);
    cudaGetSymbolAddress((void**)&zF,  g_az_ffw);
    cudaGetSymbolAddress((void**)&xb,  g_x);
    cudaGetSymbolAddress((void**)&qB,  g_q);
    cudaGetSymbolAddress((void**)&kB,  g_k);
    cudaGetSymbolAddress((void**)&vB,  g_v);
    cudaGetSymbolAddress((void**)&gB,  g_gate);
    cudaGetSymbolAddress((void**)&atB, g_attn);
    cudaGetSymbolAddress((void**)&uB,  g_u);
    cudaGetSymbolAddress((void**)&cB,  g_c);
    cudaGetSymbolAddress((void**)&pwB, g_pw);

    // enable large dynamic smem for attention kernel (host-side attr, capture-safe)
    static const int att_smem = (32*49 + 128*49 + 32*SP_STRIDE + 64) * 4;
    cudaFuncSetAttribute(attn2_kernel, cudaFuncAttributeMaxDynamicSharedMemorySize, att_smem);

    // residual stream lives in d_out
    cudaMemcpyAsync(out, act, (size_t)NC * sizeof(float), cudaMemcpyDeviceToDevice, 0);

    // row stats for LayerNorms folded into GEMM A-loads
    rowstats_kernel<<<(NT + 7) / 8, 256>>>(sc, scm, scr, NT, CSD);
    rowstats_kernel<<<(NN + 7) / 8, 256>>>(pc, pm, pr, NN, CPD);

    // pair logits: LN(pair_cond)*pair_ln_scale @ W -> g_pl [L,H,Nq,Nk] (transposed write)
    repack_pw_kernel<<<64, 256>>>(pw, pwB);
    gemmT(pc, pwB, pl, NN, 128, 128, pm, pr, plsc, 0, 0, 0, 0, 0, 1,
          1, 0, 0, 0, 0);

    // per-layer conditioning, batched across layers via gridDim.z
    const long sW = (long)CSD * CD;
    gemmT(sc, a_csw, sA, NT, CD, CSD, scm, scr, a_cln, 0, a_csb, 1, 0, 0, 0,
          LL, sW, NC, CD, CSD);
    gemmT(sc, a_cbw, kA, NT, CD, CSD, scm, scr, a_cln, 0, 0, 0, 0, 0, 0,
          LL, sW, NC, 0, CSD);
    gemmT(sc, a_azw, zA, NT, CD, CSD, 0, 0, 0, 0, a_azb, 1, 0, 0, 0,
          LL, sW, NC, CD, 0);
    gemmT(sc, f_csw, sF, NT, CD, CSD, scm, scr, f_cln, 0, f_csb, 1, 0, 0, 0,
          LL, sW, NC, CD, CSD);
    gemmT(sc, f_cbw, kF, NT, CD, CSD, scm, scr, f_cln, 0, 0, 0, 0, 0, 0,
          LL, sW, NC, 0, CSD);
    gemmT(sc, f_azw, zF, NT, CD, CSD, 0, 0, 0, 0, f_azb, 1, 0, 0, 0,
          LL, sW, NC, CD, 0);

    // transformer layers
    for(int l = 0; l < LL; l++){
        adaln_apply_kernel<<<NT, 256>>>(out, sA + (size_t)l*NC, kA + (size_t)l*NC, xb);

        gemmT(xb, qw + (size_t)l*NC, qB, NT, CD, CD, 0,0,0,0, qb + l*CD, 0, 0, 0, 0, 1,0,0,0,0);
        gemmT(xb, kw + (size_t)l*NC, kB, NT, CD, CD, 0,0,0,0, 0, 0, 0, 0, 0, 1,0,0,0,0);
        gemmT(xb, vw + (size_t)l*NC, vB, NT, CD, CD, 0,0,0,0, 0, 0, 0, 0, 0, 1,0,0,0,0);
        gemmT(xb, gw + (size_t)l*NC, gB, NT, CD, CD, 0,0,0,0, gb + l*CD, 1, 0, 0, 0, 1,0,0,0,0);

        attn2_kernel<<<dim3(NT/32, HH), 256, att_smem>>>(
            qB, kB, vB, pl + (size_t)l*16*NC, mask, atB);

        // a += sig_az_attn * ((attn*gate) @ out_w)
        gemmT(atB, ow + (size_t)l*NC, out, NT, CD, CD, 0,0,0, gB, 0, 0,
              zA + (size_t)l*NC, 1, 0, 1,0,0,0,0);

        adaln_apply_kernel<<<NT, 256>>>(out, sF + (size_t)l*NC, kF + (size_t)l*NC, xb);

        gemmT(xb, t1 + (size_t)l*CD*2*FD, uB, NT, 2*FD, CD, 0,0,0,0, 0, 0, 0, 0, 0, 1,0,0,0,0);
        glu_kernel<<<(768*1536)/256, 256>>>(uB, cB);

        // a += sig_az_ffw * (c @ t2)
        gemmT(cB, t2 + (size_t)l*FD*CD, out, NT, CD, FD, 0,0,0,0, 0, 0,
              zF + (size_t)l*NC, 1, 0, 1,0,0,0,0);
    }
}

// round 11
// speedup vs baseline: 2.3257x; 1.1393x over previous
#include <cuda_runtime.h>
#include <math.h>
#include <stdint.h>

// Problem constants
#define NT 768          // tokens
#define CD 768          // channels
#define CSD 384         // single_cond channels
#define CPD 128         // pair channels
#define HH 16           // heads
#define KDIM 48         // head dim
#define FD 1536         // ffn intermediate
#define LL 8            // layers
#define NC (768*768)
#define NN (768*768)    // pair rows

// ---------------- static device scratch ----------------
__device__ float g_pl[LL*16*768*768];        // [L,H,Nq,Nk] pair logits, 302MB
__device__ float g_pmean[NN];
__device__ float g_prstd[NN];
__device__ float g_scmean[NT];
__device__ float g_scrstd[NT];
__device__ float g_sig_attn[LL*NC];
__device__ float g_skip_attn[LL*NC];
__device__ float g_az_attn[LL*NC];
__device__ float g_sig_ffw[LL*NC];
__device__ float g_skip_ffw[LL*NC];
__device__ float g_az_ffw[LL*NC];
__device__ float g_x[NC];
__device__ float g_qkvg[4*NC];               // q | k | v | gate contiguous
__device__ float g_attn[NC];
__device__ float g_u[768*3072];
__device__ float g_c[768*1536];
__device__ float g_pw[128*128];

__device__ __forceinline__ float sigf(float x){ return 1.0f/(1.0f+__expf(-x)); }

// pack two f32 into bf16x2 (lo -> low half)
__device__ __forceinline__ uint32_t pkbf(float lo, float hi){
    uint32_t r; asm("cvt.rn.bf16x2.f32 %0, %1, %2;" : "=r"(r) : "f"(hi), "f"(lo));
    return r;
}

__device__ __forceinline__ float warp_sum(float v){
    #pragma unroll
    for(int o=16;o;o>>=1) v += __shfl_xor_sync(0xffffffffu, v, o);
    return v;
}
__device__ __forceinline__ float warp_max(float v){
    #pragma unroll
    for(int o=16;o;o>>=1) v = fmaxf(v, __shfl_xor_sync(0xffffffffu, v, o));
    return v;
}

// ---------------- row stats (mean, rstd) ----------------
__global__ void rowstats_kernel(const float* __restrict__ X, float* __restrict__ mean,
                                float* __restrict__ rstd, int rows, int cols){
    int row = blockIdx.x * (blockDim.x >> 5) + (threadIdx.x >> 5);
    if(row >= rows) return;
    int lane = threadIdx.x & 31;
    const float* x = X + (size_t)row * cols;
    float s = 0.f, sq = 0.f;
    for(int c = lane; c < cols; c += 32){ float v = x[c]; s += v; sq += v*v; }
    s = warp_sum(s); sq = warp_sum(sq);
    if(lane == 0){
        float m = s / cols;
        float var = sq / cols - m*m;
        if(var < 0.f) var = 0.f;
        mean[row] = m;
        rstd[row] = rsqrtf(var + 1e-5f);
    }
}

// ---------------- repack pair_w [NSB,CP,S,H] -> B[c][n] ----------------
__global__ void repack_pw_kernel(const float* __restrict__ pw, float* __restrict__ out){
    int idx = blockIdx.x * blockDim.x + threadIdx.x;
    if(idx >= 128*128) return;
    int c = idx >> 7, r = idx & 127;
    int sb = r >> 6, j = r & 63;
    out[idx] = pw[sb*8192 + c*64 + j];
}

// ================= BF16 tensor-core GEMM =================
// Block 64x64, K-step 32, 128 threads (4 warps as 2x2 of 32x32 warp tiles).
// m16n8k16 bf16 mma, fp32 accum. Register-prefetch pipeline on global loads.
__global__ void __launch_bounds__(128) gemm_bf16_kernel(
    const float* __restrict__ A, const float* __restrict__ B, float* __restrict__ C,
    int M, int N, int K,
    const float* __restrict__ amean, const float* __restrict__ arstd,
    const float* __restrict__ ascale, const float* __restrict__ amul,
    const float* __restrict__ bias, int do_sig,
    const float* __restrict__ egate, int do_acc, int do_transc,
    long sB, long sC, long sBias, long sScale,
    const float* __restrict__ B1, const float* __restrict__ B2,
    const float* __restrict__ B3, const float* __restrict__ bias3, int multi)
{
    __shared__ __align__(16) char sraw[64*68*4];       // 17408 B
    uint32_t (*As)[72] = (uint32_t(*)[72])sraw;        // [16][72]  4608 B
    uint32_t (*Bs)[20] = (uint32_t(*)[20])(sraw+4608); // [64][20]  5120 B

    const int z = blockIdx.z;
    const float* Bp;
    const float* biasp;
    int sig;
    if(multi){
        Bp    = (z==0)?B : (z==1)?B1 : (z==2)?B2 : B3;
        biasp = (z==0)?bias : (z==3)?bias3 : (const float*)0;
        sig   = (z==3);
    } else {
        Bp    = B + (size_t)z * sB;
        biasp = bias ? bias + (size_t)z * sBias : (const float*)0;
        sig   = do_sig;
    }
    float* Cp = C + (size_t)z * sC;
    const float* scalep = ascale ? ascale + (size_t)z * sScale : (const float*)0;

    const int tid  = threadIdx.x;
    const int m0   = blockIdx.x * 64;
    const int n0   = blockIdx.y * 64;
    const int warp = tid >> 5, lane = tid & 31;
    const int wm   = warp >> 1, wn = warp & 1;         // 2x2 warp grid, 32x32 tiles
    const int lr   = lane >> 2, lc = lane & 3;

    // A loader: row arow, k-chunks {ka..ka+7, 16+ka..16+ka+7}
    const int arow = tid & 63;
    const int ka   = (tid >> 6) * 8;
    float am = 0.f, ar = 1.f;
    if(amean){ am = amean[m0 + arow]; ar = arstd[m0 + arow]; }
    const float* Aptr = A + (size_t)(m0 + arow) * K;
    const float* Mptr = amul ? amul + (size_t)(m0 + arow) * K : (const float*)0;

    // B loader slots: slot = tid -> (kp = tid&15, n4 = (tid>>4)*4),
    //                 slot = tid+128 -> same kp, n4+32. Same k rows, shifted columns.
    const int kp0 = tid & 15;
    const int n40 = (tid >> 4) * 4;
    const int n41 = n40 + 32;

    float aPf[16], bPf[16];
    float acc[2][4][4];
    #pragma unroll
    for(int t=0;t<2;t++)
        #pragma unroll
        for(int j=0;j<4;j++){ acc[t][j][0]=0.f; acc[t][j][1]=0.f; acc[t][j][2]=0.f; acc[t][j][3]=0.f; }

    // ---- prologue: prefetch tile 0 ----
    {
        #pragma unroll
        for(int s2=0;s2<2;s2++){
            *(float4*)&aPf[s2*8]   = *(const float4*)(Aptr + s2*16 + ka);
            *(float4*)&aPf[s2*8+4] = *(const float4*)(Aptr + s2*16 + ka + 4);
        }
        *(float4*)&bPf[0]  = *(const float4*)(Bp + (size_t)(2*kp0  )*N + n0+n40);
        *(float4*)&bPf[4]  = *(const float4*)(Bp + (size_t)(2*kp0+1)*N + n0+n40);
        *(float4*)&bPf[8]  = *(const float4*)(Bp + (size_t)(2*kp0  )*N + n0+n41);
        *(float4*)&bPf[12] = *(const float4*)(Bp + (size_t)(2*kp0+1)*N + n0+n41);
    }

    for(int k0 = 0; k0 < K; k0 += 32){
        // ---- store prefetched tile (for k0) into smem ----
        {
            #pragma unroll
            for(int s2=0;s2<2;s2++){
                float av[8];
                #pragma unroll
                for(int i=0;i<8;i++) av[i] = aPf[s2*8+i];
                const int kg = k0 + s2*16 + ka;
                if(amean){
                    #pragma unroll
                    for(int i=0;i<8;i++) av[i] = (av[i]-am)*ar;
                }
                if(scalep){
                    float4 s0 = *(const float4*)(scalep + kg);
                    float4 s1 = *(const float4*)(scalep + kg + 4);
                    av[0]*=s0.x; av[1]*=s0.y; av[2]*=s0.z; av[3]*=s0.w;
                    av[4]*=s1.x; av[5]*=s1.y; av[6]*=s1.z; av[7]*=s1.w;
                }
                if(Mptr){
                    float4 m0v = *(const float4*)(Mptr + kg);
                    float4 m1v = *(const float4*)(Mptr + kg + 4);
                    av[0]*=m0v.x; av[1]*=m0v.y; av[2]*=m0v.z; av[3]*=m0v.w;
                    av[4]*=m1v.x; av[5]*=m1v.y; av[6]*=m1v.z; av[7]*=m1v.w;
                }
                const int kpb = (s2*16 + ka) >> 1;
                #pragma unroll
                for(int i=0;i<4;i++) As[kpb+i][arow] = pkbf(av[2*i], av[2*i+1]);
            }
            #pragma unroll
            for(int j=0;j<4;j++) Bs[n40+j][kp0] = pkbf(bPf[j],   bPf[4+j]);
            #pragma unroll
            for(int j=0;j<4;j++) Bs[n41+j][kp0] = pkbf(bPf[8+j], bPf[12+j]);
        }
        __syncthreads();

        // ---- prefetch next tile into regs ----
        const int kn = k0 + 32;
        if(kn < K){
            #pragma unroll
            for(int s2=0;s2<2;s2++){
                *(float4*)&aPf[s2*8]   = *(const float4*)(Aptr + kn + s2*16 + ka);
                *(float4*)&aPf[s2*8+4] = *(const float4*)(Aptr + kn + s2*16 + ka + 4);
            }
            *(float4*)&bPf[0]  = *(const float4*)(Bp + (size_t)(kn+2*kp0  )*N + n0+n40);
            *(float4*)&bPf[4]  = *(const float4*)(Bp + (size_t)(kn+2*kp0+1)*N + n0+n40);
            *(float4*)&bPf[8]  = *(const float4*)(Bp + (size_t)(kn+2*kp0  )*N + n0+n41);
            *(float4*)&bPf[12] = *(const float4*)(Bp + (size_t)(kn+2*kp0+1)*N + n0+n41);
        }

        // ---- compute on smem tile ----
        #pragma unroll
        for(int s=0;s<2;s++){
            const int kpo = s*8;
            uint32_t af[2][4];
            #pragma unroll
            for(int t=0;t<2;t++){
                const int mb = wm*32 + t*16;
                af[t][0] = As[kpo+lc  ][mb+lr  ];
                af[t][1] = As[kpo+lc  ][mb+lr+8];
                af[t][2] = As[kpo+lc+4][mb+lr  ];
                af[t][3] = As[kpo+lc+4][mb+lr+8];
            }
            #pragma unroll
            for(int j=0;j<4;j++){
                const int nb = wn*32 + j*8 + lr;
                uint32_t b0 = Bs[nb][kpo+lc];
                uint32_t b1 = Bs[nb][kpo+lc+4];
                #pragma unroll
                for(int t=0;t<2;t++){
                    asm volatile(
                        "mma.sync.aligned.m16n8k16.row.col.f32.bf16.bf16.f32 "
                        "{%0,%1,%2,%3}, {%4,%5,%6,%7}, {%8,%9}, {%0,%1,%2,%3};"
                        : "+f"(acc[t][j][0]), "+f"(acc[t][j][1]),
                          "+f"(acc[t][j][2]), "+f"(acc[t][j][3])
                        : "r"(af[t][0]), "r"(af[t][1]), "r"(af[t][2]), "r"(af[t][3]),
                          "r"(b0), "r"(b1));
                }
            }
        }
        __syncthreads();
    }

    // ---- epilogue ----
    if(!do_transc){
        #pragma unroll
        for(int t=0;t<2;t++){
            #pragma unroll
            for(int j=0;j<4;j++){
                const int rr = m0 + wm*32 + t*16 + lr;
                const int cc = n0 + wn*32 + j*8 + 2*lc;
                float2 r0 = make_float2(acc[t][j][0], acc[t][j][1]);
                float2 r1 = make_float2(acc[t][j][2], acc[t][j][3]);
                if(biasp){ float2 bv = *(const float2*)(biasp + cc);
                           r0.x+=bv.x; r0.y+=bv.y; r1.x+=bv.x; r1.y+=bv.y; }
                if(sig){ r0.x=sigf(r0.x); r0.y=sigf(r0.y); r1.x=sigf(r1.x); r1.y=sigf(r1.y); }
                if(egate){
                    float2 g0 = *(const float2*)(egate + (size_t)rr*N + cc);
                    float2 g1 = *(const float2*)(egate + (size_t)(rr+8)*N + cc);
                    r0.x*=g0.x; r0.y*=g0.y; r1.x*=g1.x; r1.y*=g1.y;
                }
                float* cp0 = Cp + (size_t)rr*N + cc;
                float* cp1 = Cp + (size_t)(rr+8)*N + cc;
                if(do_acc){
                    float2 c0 = *(const float2*)cp0; r0.x+=c0.x; r0.y+=c0.y;
                    float2 c1 = *(const float2*)cp1; r1.x+=c1.x; r1.y+=c1.y;
                }
                *(float2*)cp0 = r0;
                *(float2*)cp1 = r1;
            }
        }
    } else {
        // stage in smem (reuse sraw), write coalesced columns-of-C as rows
        float (*sCt)[68] = (float(*)[68])sraw;
        __syncthreads();
        #pragma unroll
        for(int t=0;t<2;t++){
            #pragma unroll
            for(int j=0;j<4;j++){
                const int rr = wm*32 + t*16 + lr;
                const int cc = wn*32 + j*8 + 2*lc;
                sCt[cc  ][rr  ] = acc[t][j][0];
                sCt[cc+1][rr  ] = acc[t][j][1];
                sCt[cc  ][rr+8] = acc[t][j][2];
                sCt[cc+1][rr+8] = acc[t][j][3];
            }
        }
        __syncthreads();
        #pragma unroll
        for(int it=0; it<8; it++){
            int idx = tid + it*128;           // 1024 float4 slots
            int n = idx >> 4, mq = (idx & 15) * 4;
            float4 v = *(const float4*)&sCt[n][mq];
            *(float4*)(Cp + (size_t)(n0+n)*M + m0 + mq) = v;
        }
    }
}

// ---------------- fused adaLN apply: x = sig * LN(a) + skip ----------------
__global__ void __launch_bounds__(256) adaln_apply_kernel(
    const float* __restrict__ a, const float* __restrict__ sig,
    const float* __restrict__ skip, float* __restrict__ x)
{
    __shared__ float sred[32];
    int row = blockIdx.x;
    const float* arow = a + (size_t)row * 768;
    int t = threadIdx.x, lane = t & 31, w = t >> 5;
    float v0 = arow[t], v1 = arow[t+256], v2 = arow[t+512];
    float s = warp_sum(v0+v1+v2);
    if(lane==0) sred[w] = s;
    __syncthreads();
    if(t < 32){ float q = (t < 8) ? sred[t] : 0.f; sred[t] = warp_sum(q); }
    __syncthreads();
    float m = sred[0] * (1.f/768.f);
    __syncthreads();
    float d0 = v0-m, d1 = v1-m, d2 = v2-m;
    float vv = warp_sum(d0*d0 + d1*d1 + d2*d2);
    if(lane==0) sred[w] = vv;
    __syncthreads();
    if(t < 32){ float q = (t < 8) ? sred[t] : 0.f; sred[t] = warp_sum(q); }
    __syncthreads();
    float rs = rsqrtf(sred[0] * (1.f/768.f) + 1e-5f);
    size_t base = (size_t)row * 768 + t;
    x[base]      = sig[base]      * (d0*rs) + skip[base];
    x[base+256]  = sig[base+256]  * (d1*rs) + skip[base+256];
    x[base+512]  = sig[base+512]  * (d2*rs) + skip[base+512];
}

// ================= attention: block per (32-query tile, head) =================
#define SP_STRIDE 772
__global__ void __launch_bounds__(256) attn2_kernel(
    const float* __restrict__ Q, const float* __restrict__ Kx,
    const float* __restrict__ V, const float* __restrict__ pl,
    const float* __restrict__ mask, float* __restrict__ O)
{
    extern __shared__ float sm[];
    float* sQ   = sm;                          // 32*49
    float* sKV  = sQ + 32*49;                  // 128*49
    float* sP   = sKV + 128*49;                // 32*772
    float* sSum = sP + 32*SP_STRIDE;           // 32

    const int qt = blockIdx.x, h = blockIdx.y;
    const int q0 = qt * 32;
    const int tid = threadIdx.x;
    const float scale = rsqrtf(48.f);

    for(int i = tid; i < 32*48; i += 256){
        int q = i / 48, d = i % 48;
        sQ[q*49 + d] = Q[(size_t)(q0+q)*768 + h*48 + d];
    }

    const int qa = (tid & 7) * 4;
    const int kaa = (tid >> 3) * 4;
    for(int kt = 0; kt < 6; kt++){
        __syncthreads();
        for(int i = tid; i < 128*48; i += 256){
            int k = i / 48, d = i % 48;
            sKV[k*49 + d] = Kx[(size_t)(kt*128 + k)*768 + h*48 + d];
        }
        __syncthreads();
        float s[4][4];
        #pragma unroll
        for(int i=0;i<4;i++){ s[i][0]=0.f; s[i][1]=0.f; s[i][2]=0.f; s[i][3]=0.f; }
        #pragma unroll 4
        for(int d = 0; d < 48; d++){
            float qv[4], kv[4];
            #pragma unroll
            for(int i=0;i<4;i++) qv[i] = sQ[(qa+i)*49 + d];
            #pragma unroll
            for(int j=0;j<4;j++) kv[j] = sKV[(kaa+j)*49 + d];
            #pragma unroll
            for(int i=0;i<4;i++)
                #pragma unroll
                for(int j=0;j<4;j++) s[i][j] += qv[i]*kv[j];
        }
        int kg = kt*128 + kaa;
        float4 mk = *(const float4*)(mask + kg);
        float bb[4] = {1e9f*(mk.x-1.f), 1e9f*(mk.y-1.f), 1e9f*(mk.z-1.f), 1e9f*(mk.w-1.f)};
        #pragma unroll
        for(int i=0;i<4;i++){
            float4 plv = *(const float4*)(pl + ((size_t)h*768 + q0+qa+i)*768 + kg);
            float* prow = sP + (qa+i)*SP_STRIDE + kg;
            prow[0] = s[i][0]*scale + plv.x + bb[0];
            prow[1] = s[i][1]*scale + plv.y + bb[1];
            prow[2] = s[i][2]*scale + plv.z + bb[2];
            prow[3] = s[i][3]*scale + plv.w + bb[3];
        }
    }
    __syncthreads();

    {
        int warp = tid >> 5, lane = tid & 31;
        for(int r = warp*4; r < warp*4 + 4; r++){
            float* row = sP + r*SP_STRIDE;
            float mx = -1e30f;
            for(int k = lane; k < 768; k += 32) mx = fmaxf(mx, row[k]);
            mx = warp_max(mx);
            float sum = 0.f;
            for(int k = lane; k < 768; k += 32){
                float e = __expf(row[k] - mx);
                row[k] = e;
                sum += e;
            }
            sum = warp_sum(sum);
            if(lane == 0) sSum[r] = sum;
        }
    }
    __syncthreads();

    const int g  = tid >> 7;
    const int tt = tid & 127;
    const int q  = (tt >> 3) * 2;
    const int d0 = (tt & 7) * 6;
    float oa[2][6];
    #pragma unroll
    for(int j=0;j<6;j++){ oa[0][j]=0.f; oa[1][j]=0.f; }

    for(int kt = 0; kt < 6; kt++){
        __syncthreads();
        for(int i = tid; i < 128*48; i += 256){
            int k = i / 48, d = i % 48;
            sKV[k*49 + d] = V[(size_t)(kt*128 + k)*768 + h*48 + d];
        }
        __syncthreads();
        const int kbase = kt*128 + g*64;
        const float* p0r = sP + q*SP_STRIDE + kbase;
        const float* p1r = sP + (q+1)*SP_STRIDE + kbase;
        const float* vb  = sKV + (g*64)*49 + d0;
        #pragma unroll 4
        for(int kk = 0; kk < 64; kk++){
            float p0 = p0r[kk], p1 = p1r[kk];
            const float* vr = vb + kk*49;
            #pragma unroll
            for(int j=0;j<6;j++){
                float v = vr[j];
                oa[0][j] += p0 * v;
                oa[1][j] += p1 * v;
            }
        }
    }
    __syncthreads();
    if(g == 1){
        #pragma unroll
        for(int j=0;j<6;j++){ sP[tt*12 + j] = oa[0][j]; sP[tt*12 + 6 + j] = oa[1][j]; }
    }
    __syncthreads();
    if(g == 0){
        float inv0 = 1.f / sSum[q], inv1 = 1.f / sSum[q+1];
        #pragma unroll
        for(int j=0;j<6;j++){
            float o0 = (oa[0][j] + sP[tt*12 + j])     * inv0;
            float o1 = (oa[1][j] + sP[tt*12 + 6 + j]) * inv1;
            O[(size_t)(q0+q  )*768 + h*48 + d0 + j] = o0;
            O[(size_t)(q0+q+1)*768 + h*48 + d0 + j] = o1;
        }
    }
}

// ---------------- GLU ----------------
__global__ void glu_kernel(const float* __restrict__ u, float* __restrict__ c){
    int i = blockIdx.x * blockDim.x + threadIdx.x;
    if(i >= 768*1536) return;
    int row = i / 1536, col = i % 1536;
    float a = u[(size_t)row*3072 + col];
    float b = u[(size_t)row*3072 + 1536 + col];
    c[i] = a * sigf(a) * b;
}

// ---------------- host-side GEMM launcher ----------------
static void gemmB(const float* A, const float* B, float* C, int M, int N, int K,
                  const float* amean, const float* arstd, const float* ascale,
                  const float* amul, const float* bias, int sig,
                  const float* egate, int acc, int transc,
                  int batch, long sB, long sC, long sBias, long sScale,
                  const float* B1 = 0, const float* B2 = 0, const float* B3 = 0,
                  const float* bias3 = 0, int multi = 0)
{
    dim3 g(M/64, N/64, batch);
    gemm_bf16_kernel<<<g, 128>>>(A, B, C, M, N, K, amean, arstd, ascale, amul,
                                 bias, sig, egate, acc, transc,
                                 sB, sC, sBias, sScale, B1, B2, B3, bias3, multi);
}

extern "C" void kernel_launch(void* const* d_in, const int* in_sizes, int n_in,
                              void* d_out, int out_size)
{
    const float* act   = (const float*)d_in[0];
    const float* mask  = (const float*)d_in[1];
    const float* sc    = (const float*)d_in[2];
    const float* pc    = (const float*)d_in[3];
    const float* a_cln = (const float*)d_in[4];
    const float* a_csw = (const float*)d_in[5];
    const float* a_csb = (const float*)d_in[6];
    const float* a_cbw = (const float*)d_in[7];
    const float* qw    = (const float*)d_in[8];
    const float* qb    = (const float*)d_in[9];
    const float* kw    = (const float*)d_in[10];
    const float* vw    = (const float*)d_in[11];
    const float* gw    = (const float*)d_in[12];
    const float* gb    = (const float*)d_in[13];
    const float* ow    = (const float*)d_in[14];
    const float* a_azw = (const float*)d_in[15];
    const float* a_azb = (const float*)d_in[16];
    const float* f_cln = (const float*)d_in[17];
    const float* f_csw = (const float*)d_in[18];
    const float* f_csb = (const float*)d_in[19];
    const float* f_cbw = (const float*)d_in[20];
    const float* t1    = (const float*)d_in[21];
    const float* t2    = (const float*)d_in[22];
    const float* f_azw = (const float*)d_in[23];
    const float* f_azb = (const float*)d_in[24];
    const float* plsc  = (const float*)d_in[25];
    const float* pw    = (const float*)d_in[26];
    float* out = (float*)d_out;

    float *pl, *pm, *pr, *scm, *scr;
    float *sA, *kA, *zA, *sF, *kF, *zF;
    float *xb, *qkvg, *atB, *uB, *cB, *pwB;
    cudaGetSymbolAddress((void**)&pl,   g_pl);
    cudaGetSymbolAddress((void**)&pm,   g_pmean);
    cudaGetSymbolAddress((void**)&pr,   g_prstd);
    cudaGetSymbolAddress((void**)&scm,  g_scmean);
    cudaGetSymbolAddress((void**)&scr,  g_scrstd);
    cudaGetSymbolAddress((void**)&sA,   g_sig_attn);
    cudaGetSymbolAddress((void**)&kA,   g_skip_attn);
    cudaGetSymbolAddress((void**)&zA,   g_az_attn);
    cudaGetSymbolAddress((void**)&sF,   g_sig_ffw);
    cudaGetSymbolAddress((void**)&kF,   g_skip_ffw);
    cudaGetSymbolAddress((void**)&zF,   g_az_ffw);
    cudaGetSymbolAddress((void**)&xb,   g_x);
    cudaGetSymbolAddress((void**)&qkvg, g_qkvg);
    cudaGetSymbolAddress((void**)&atB,  g_attn);
    cudaGetSymbolAddress((void**)&uB,   g_u);
    cudaGetSymbolAddress((void**)&cB,   g_c);
    cudaGetSymbolAddress((void**)&pwB,  g_pw);

    static const int att_smem = (32*49 + 128*49 + 32*SP_STRIDE + 64) * 4;
    cudaFuncSetAttribute(attn2_kernel, cudaFuncAttributeMaxDynamicSharedMemorySize, att_smem);

    cudaMemcpyAsync(out, act, (size_t)NC * sizeof(float), cudaMemcpyDeviceToDevice, 0);

    rowstats_kernel<<<(NT + 7) / 8, 256>>>(sc, scm, scr, NT, CSD);
    rowstats_kernel<<<(NN + 7) / 8, 256>>>(pc, pm, pr, NN, CPD);

    // pair logits: LN(pair_cond)*pair_ln_scale @ W -> g_pl (coalesced transposed write)
    repack_pw_kernel<<<64, 256>>>(pw, pwB);
    gemmB(pc, pwB, pl, NN, 128, 128, pm, pr, plsc, 0, 0, 0, 0, 0, 1,
          1, 0, 0, 0, 0);

    // conditioning, batched across layers via gridDim.z
    const long sW = (long)CSD * CD;
    gemmB(sc, a_csw, sA, NT, CD, CSD, scm, scr, a_cln, 0, a_csb, 1, 0, 0, 0,
          LL, sW, NC, CD, CSD);
    gemmB(sc, a_cbw, kA, NT, CD, CSD, scm, scr, a_cln, 0, 0, 0, 0, 0, 0,
          LL, sW, NC, 0, CSD);
    gemmB(sc, a_azw, zA, NT, CD, CSD, 0, 0, 0, 0, a_azb, 1, 0, 0, 0,
          LL, sW, NC, CD, 0);
    gemmB(sc, f_csw, sF, NT, CD, CSD, scm, scr, f_cln, 0, f_csb, 1, 0, 0, 0,
          LL, sW, NC, CD, CSD);
    gemmB(sc, f_cbw, kF, NT, CD, CSD, scm, scr, f_cln, 0, 0, 0, 0, 0, 0,
          LL, sW, NC, 0, CSD);
    gemmB(sc, f_azw, zF, NT, CD, CSD, 0, 0, 0, 0, f_azb, 1, 0, 0, 0,
          LL, sW, NC, CD, 0);

    for(int l = 0; l < LL; l++){
        adaln_apply_kernel<<<NT, 256>>>(out, sA + (size_t)l*NC, kA + (size_t)l*NC, xb);

        // q,k,v,gate in ONE batched launch (z selects weight/bias/sigmoid)
        gemmB(xb, qw + (size_t)l*NC, qkvg, NT, CD, CD, 0,0,0,0,
              qb + (size_t)l*CD, 0, 0, 0, 0,
              4, 0, NC, 0, 0,
              kw + (size_t)l*NC, vw + (size_t)l*NC, gw + (size_t)l*NC,
              gb + (size_t)l*CD, /*multi=*/1);

        attn2_kernel<<<dim3(NT/32, HH), 256, att_smem>>>(
            qkvg, qkvg + NC, qkvg + 2*NC, pl + (size_t)l*16*NC, mask, atB);

        // a += sig_az_attn * ((attn*gate) @ out_w)
        gemmB(atB, ow + (size_t)l*NC, out, NT, CD, CD, 0,0,0, qkvg + 3*NC, 0, 0,
              zA + (size_t)l*NC, 1, 0, 1,0,0,0,0);

        adaln_apply_kernel<<<NT, 256>>>(out, sF + (size_t)l*NC, kF + (size_t)l*NC, xb);

        gemmB(xb, t1 + (size_t)l*CD*2*FD, uB, NT, 2*FD, CD, 0,0,0,0, 0, 0, 0, 0, 0,
              1,0,0,0,0);
        glu_kernel<<<(768*1536)/256, 256>>>(uB, cB);

        // a += sig_az_ffw * (c @ t2)
        gemmB(cB, t2 + (size_t)l*FD*CD, out, NT, CD, FD, 0,0,0,0, 0, 0,
              zF + (size_t)l*NC, 1, 0, 1,0,0,0,0);
    }
}

// round 12
// speedup vs baseline: 2.5817x; 1.1100x over previous
#include <cuda_runtime.h>
#include <math.h>
#include <stdint.h>

// Problem constants
#define NT 768          // tokens
#define CD 768          // channels
#define CSD 384         // single_cond channels
#define CPD 128         // pair channels
#define HH 16           // heads
#define KDIM 48         // head dim
#define FD 1536         // ffn intermediate
#define LL 8            // layers
#define NC (768*768)
#define NN (768*768)    // pair rows

// ---- pre-tiled bf16 weight buffer offsets (uint32 units; each u32 = bf16x2) ----
#define U_SQ   294912            // 768*768/2
#define OFF_QW   0
#define OFF_KW   2359296
#define OFF_VW   4718592
#define OFF_GW   7077888
#define OFF_OW   9437184
#define OFF_T1   11796480        // 8 * 768*3072/2 = 9437184
#define OFF_T2   21233664        // 8 * 1536*768/2 = 4718592
#define OFF_ACSW 25952256        // 6 cond blocks, each 8*384*768/2 = 1179648
#define OFF_ACBW 27131904
#define OFF_AAZW 28311552
#define OFF_FCSW 29491200
#define OFF_FCBW 30670848
#define OFF_FAZW 31850496
#define OFF_PW   33030144        // 128*128/2 = 8192
#define WBF_TOTAL 33038336

// ---------------- static device scratch ----------------
__device__ float g_pl[LL*16*768*768];        // [L,H,Nq,Nk] pair logits, 302MB
__device__ uint32_t g_wbf[WBF_TOTAL];        // pre-tiled bf16 weights, 132MB
__device__ float g_pmean[NN];
__device__ float g_prstd[NN];
__device__ float g_scmean[NT];
__device__ float g_scrstd[NT];
__device__ float g_sig_attn[LL*NC];
__device__ float g_skip_attn[LL*NC];
__device__ float g_az_attn[LL*NC];
__device__ float g_sig_ffw[LL*NC];
__device__ float g_skip_ffw[LL*NC];
__device__ float g_az_ffw[LL*NC];
__device__ float g_x[NC];
__device__ float g_qkvg[4*NC];               // q | k | v | gate contiguous
__device__ float g_attn[NC];
__device__ float g_u[768*3072];
__device__ float g_c[768*1536];

__device__ __forceinline__ float sigf(float x){ return 1.0f/(1.0f+__expf(-x)); }

// pack two f32 into bf16x2 (lo -> low half)
__device__ __forceinline__ uint32_t pkbf(float lo, float hi){
    uint32_t r; asm("cvt.rn.bf16x2.f32 %0, %1, %2;" : "=r"(r) : "f"(hi), "f"(lo));
    return r;
}

__device__ __forceinline__ float warp_sum(float v){
    #pragma unroll
    for(int o=16;o;o>>=1) v += __shfl_xor_sync(0xffffffffu, v, o);
    return v;
}
__device__ __forceinline__ float warp_max(float v){
    #pragma unroll
    for(int o=16;o;o>>=1) v = fmaxf(v, __shfl_xor_sync(0xffffffffu, v, o));
    return v;
}

// ---------------- row stats (mean, rstd) ----------------
__global__ void rowstats_kernel(const float* __restrict__ X, float* __restrict__ mean,
                                float* __restrict__ rstd, int rows, int cols){
    int row = blockIdx.x * (blockDim.x >> 5) + (threadIdx.x >> 5);
    if(row >= rows) return;
    int lane = threadIdx.x & 31;
    const float* x = X + (size_t)row * cols;
    float s = 0.f, sq = 0.f;
    for(int c = lane; c < cols; c += 32){ float v = x[c]; s += v; sq += v*v; }
    s = warp_sum(s); sq = warp_sum(sq);
    if(lane == 0){
        float m = s / cols;
        float var = sq / cols - m*m;
        if(var < 0.f) var = 0.f;
        mean[row] = m;
        rstd[row] = rsqrtf(var + 1e-5f);
    }
}

// ---------------- weight conversion: f32 [K][N] -> pre-tiled bf16 fragments ----
// tile = [64 n][32 k] -> 1024 u32 laid out [s(2)][nblk(8)][lane(32)][reg(2)];
// tiles ordered kt-major within each nt column block.
__global__ void conv_w_kernel(const float* __restrict__ W, const float* __restrict__ rs,
                              uint32_t* __restrict__ out, int K, int N,
                              long sW, long sRS){
    int z = blockIdx.z;
    const float* Wp = W + (size_t)z * sW;
    const float* rp = rs ? rs + (size_t)z * sRS : (const float*)0;
    long total = (long)K * N / 2;
    long gid = (long)blockIdx.x * 256 + threadIdx.x;
    if(gid >= total) return;
    int k2 = (int)(gid / N), n = (int)(gid - (long)k2 * N);
    int k = k2 * 2;
    float lo = Wp[(size_t)k*N + n], hi = Wp[(size_t)(k+1)*N + n];
    if(rp){ lo *= rp[k]; hi *= rp[k+1]; }
    int kt = k >> 5, kk = k & 31, s = kk >> 4, p = (kk & 15) >> 1;
    int ntl = n >> 6, nn = n & 63, nblk = nn >> 3;
    int lane = (nn & 7) * 4 + (p & 3), reg = p >> 2;
    int KT = K >> 5;
    size_t idx = (size_t)(ntl * KT + kt) * 1024 + s*512 + nblk*64 + lane*2 + reg;
    out[(size_t)z * (size_t)(K*N/2) + idx] = pkbf(lo, hi);
}

// pair_w [NSB,CP,S,H] -> pre-tiled bf16 [c][n], n=(sb*4+s)*16+h, row-scaled by plsc
__global__ void conv_pw_kernel(const float* __restrict__ pw,
                               const float* __restrict__ plsc,
                               uint32_t* __restrict__ out){
    int gid = blockIdx.x * 256 + threadIdx.x;
    if(gid >= 8192) return;
    int k2 = gid >> 7, n = gid & 127;
    int k = k2 * 2;
    int sb = n >> 6, j = n & 63;
    float lo = pw[sb*8192 + k*64 + j]     * plsc[k];
    float hi = pw[sb*8192 + (k+1)*64 + j] * plsc[k+1];
    int kt = k >> 5, kk = k & 31, s = kk >> 4, p = (kk & 15) >> 1;
    int ntl = n >> 6, nn = n & 63, nblk = nn >> 3;
    int lane = (nn & 7) * 4 + (p & 3), reg = p >> 2;
    size_t idx = (size_t)(ntl * 4 + kt) * 1024 + s*512 + nblk*64 + lane*2 + reg;
    out[idx] = pkbf(lo, hi);
}

// ================= BF16 tensor-core GEMM v2 =================
// Block 64x64, K-step 32, 128 threads (2x2 warps of 32x32 tiles).
// A: f32 [M][K] with fused per-row LN (amean/arstd) and elementwise amul.
// B: PRE-TILED bf16 fragments (see conv_w_kernel) -> pure LDG.128/STS.128 copy.
// Fragment-order smem: a-frag = 1 LDS.128, b-frag = 1 LDS.64.
__global__ void __launch_bounds__(128) gemm2_kernel(
    const float* __restrict__ A, const uint32_t* __restrict__ Bt, float* __restrict__ C,
    int M, int N, int K,
    const float* __restrict__ amean, const float* __restrict__ arstd,
    const float* __restrict__ amul,
    const float* __restrict__ bias, int do_sig,
    const float* __restrict__ egate, int do_acc, int do_transc,
    long sBt, long sC, long sBias,
    const float* __restrict__ bias3, int multi)
{
    __shared__ __align__(16) char sraw[17408];
    uint32_t* As2 = (uint32_t*)sraw;              // [2][4][32][4] = 1024 u32
    uint32_t* Bs2 = (uint32_t*)(sraw + 4096);     // [2][8][32][2] = 1024 u32

    const int z = blockIdx.z;
    const uint32_t* Bp = Bt + (size_t)z * sBt;
    const float* biasp;
    int sig;
    if(multi){
        biasp = (z==0) ? bias : (z==3 ? bias3 : (const float*)0);
        sig   = (z==3);
    } else {
        biasp = bias ? bias + (size_t)z * sBias : (const float*)0;
        sig   = do_sig;
    }
    float* Cp = C + (size_t)z * sC;

    const int tid  = threadIdx.x;
    const int m0   = blockIdx.x * 64;
    const int nt   = blockIdx.y;
    const int n0   = nt * 64;
    const int KT   = K >> 5;
    const int warp = tid >> 5, lane = tid & 31;
    const int wm   = warp >> 1, wn = warp & 1;
    const int lr   = lane >> 2, lc = lane & 3;

    // A loader: row arow, k-chunks ka..ka+7 in each 16-k slice
    const int arow = tid & 63;
    const int ka   = (tid >> 6) * 8;
    float am = 0.f, ar = 1.f;
    if(amean){ am = amean[m0 + arow]; ar = arstd[m0 + arow]; }
    const float* Aptr = A + (size_t)(m0 + arow) * K;
    const float* Mptr = amul ? amul + (size_t)(m0 + arow) * K : (const float*)0;
    const int aLaneB = (arow & 7) * 4;
    const int aReg   = ((ka >> 3) << 1) + ((arow >> 3) & 1);
    const int aMblk  = arow >> 4;

    const uint32_t* Btile = Bp + (size_t)nt * KT * 1024;

    float aPf[16];
    uint4 bPf0, bPf1;
    float acc[2][4][4];
    #pragma unroll
    for(int t=0;t<2;t++)
        #pragma unroll
        for(int j=0;j<4;j++){ acc[t][j][0]=0.f; acc[t][j][1]=0.f; acc[t][j][2]=0.f; acc[t][j][3]=0.f; }

    // ---- prologue prefetch ----
    #pragma unroll
    for(int s2=0;s2<2;s2++){
        *(float4*)&aPf[s2*8]   = *(const float4*)(Aptr + s2*16 + ka);
        *(float4*)&aPf[s2*8+4] = *(const float4*)(Aptr + s2*16 + ka + 4);
    }
    bPf0 = *(const uint4*)(Btile + tid*8);
    bPf1 = *(const uint4*)(Btile + tid*8 + 4);

    for(int kt = 0; kt < KT; kt++){
        // ---- store A (with transforms) in fragment order ----
        #pragma unroll
        for(int s2=0;s2<2;s2++){
            float av[8];
            #pragma unroll
            for(int i=0;i<8;i++) av[i] = aPf[s2*8+i];
            if(amean){
                #pragma unroll
                for(int i=0;i<8;i++) av[i] = (av[i]-am)*ar;
            }
            if(Mptr){
                const int kg = kt*32 + s2*16 + ka;
                float4 m0v = *(const float4*)(Mptr + kg);
                float4 m1v = *(const float4*)(Mptr + kg + 4);
                av[0]*=m0v.x; av[1]*=m0v.y; av[2]*=m0v.z; av[3]*=m0v.w;
                av[4]*=m1v.x; av[5]*=m1v.y; av[6]*=m1v.z; av[7]*=m1v.w;
            }
            #pragma unroll
            for(int i=0;i<4;i++)
                As2[s2*512 + aMblk*128 + (aLaneB+i)*4 + aReg] = pkbf(av[2*i], av[2*i+1]);
        }
        // ---- store B (pure copy, already fragment-ordered) ----
        *(uint4*)&Bs2[tid*8]     = bPf0;
        *(uint4*)&Bs2[tid*8 + 4] = bPf1;
        __syncthreads();

        // ---- prefetch next tile ----
        if(kt+1 < KT){
            const float* An = Aptr + (kt+1)*32;
            #pragma unroll
            for(int s2=0;s2<2;s2++){
                *(float4*)&aPf[s2*8]   = *(const float4*)(An + s2*16 + ka);
                *(float4*)&aPf[s2*8+4] = *(const float4*)(An + s2*16 + ka + 4);
            }
            const uint32_t* Bn = Btile + (size_t)(kt+1)*1024;
            bPf0 = *(const uint4*)(Bn + tid*8);
            bPf1 = *(const uint4*)(Bn + tid*8 + 4);
        }

        // ---- compute: 2 k16 slices ----
        #pragma unroll
        for(int s=0;s<2;s++){
            uint32_t af[2][4];
            #pragma unroll
            for(int t=0;t<2;t++){
                uint4 v = *(const uint4*)&As2[s*512 + (wm*2+t)*128 + lane*4];
                af[t][0]=v.x; af[t][1]=v.y; af[t][2]=v.z; af[t][3]=v.w;
            }
            #pragma unroll
            for(int j=0;j<4;j++){
                uint2 bv = *(const uint2*)&Bs2[s*512 + (wn*4+j)*64 + lane*2];
                #pragma unroll
                for(int t=0;t<2;t++){
                    asm volatile(
                        "mma.sync.aligned.m16n8k16.row.col.f32.bf16.bf16.f32 "
                        "{%0,%1,%2,%3}, {%4,%5,%6,%7}, {%8,%9}, {%0,%1,%2,%3};"
                        : "+f"(acc[t][j][0]), "+f"(acc[t][j][1]),
                          "+f"(acc[t][j][2]), "+f"(acc[t][j][3])
                        : "r"(af[t][0]), "r"(af[t][1]), "r"(af[t][2]), "r"(af[t][3]),
                          "r"(bv.x), "r"(bv.y));
                }
            }
        }
        __syncthreads();
    }

    // ---- epilogue ----
    if(!do_transc){
        #pragma unroll
        for(int t=0;t<2;t++){
            #pragma unroll
            for(int j=0;j<4;j++){
                const int rr = m0 + wm*32 + t*16 + lr;
                const int cc = n0 + wn*32 + j*8 + 2*lc;
                float2 r0 = make_float2(acc[t][j][0], acc[t][j][1]);
                float2 r1 = make_float2(acc[t][j][2], acc[t][j][3]);
                if(biasp){ float2 bv = *(const float2*)(biasp + cc);
                           r0.x+=bv.x; r0.y+=bv.y; r1.x+=bv.x; r1.y+=bv.y; }
                if(sig){ r0.x=sigf(r0.x); r0.y=sigf(r0.y); r1.x=sigf(r1.x); r1.y=sigf(r1.y); }
                if(egate){
                    float2 g0 = *(const float2*)(egate + (size_t)rr*N + cc);
                    float2 g1 = *(const float2*)(egate + (size_t)(rr+8)*N + cc);
                    r0.x*=g0.x; r0.y*=g0.y; r1.x*=g1.x; r1.y*=g1.y;
                }
                float* cp0 = Cp + (size_t)rr*N + cc;
                float* cp1 = Cp + (size_t)(rr+8)*N + cc;
                if(do_acc){
                    float2 c0 = *(const float2*)cp0; r0.x+=c0.x; r0.y+=c0.y;
                    float2 c1 = *(const float2*)cp1; r1.x+=c1.x; r1.y+=c1.y;
                }
                *(float2*)cp0 = r0;
                *(float2*)cp1 = r1;
            }
        }
    } else {
        // stage in smem, write coalesced columns-of-C as rows
        float (*sCt)[68] = (float(*)[68])sraw;
        #pragma unroll
        for(int t=0;t<2;t++){
            #pragma unroll
            for(int j=0;j<4;j++){
                const int rr = wm*32 + t*16 + lr;
                const int cc = wn*32 + j*8 + 2*lc;
                sCt[cc  ][rr  ] = acc[t][j][0];
                sCt[cc+1][rr  ] = acc[t][j][1];
                sCt[cc  ][rr+8] = acc[t][j][2];
                sCt[cc+1][rr+8] = acc[t][j][3];
            }
        }
        __syncthreads();
        #pragma unroll
        for(int it=0; it<8; it++){
            int idx = tid + it*128;
            int n = idx >> 4, mq = (idx & 15) * 4;
            float4 v = *(const float4*)&sCt[n][mq];
            *(float4*)(Cp + (size_t)(n0+n)*M + m0 + mq) = v;
        }
    }
}

// ---------------- fused adaLN apply: x = sig * LN(a) + skip ----------------
__global__ void __launch_bounds__(256) adaln_apply_kernel(
    const float* __restrict__ a, const float* __restrict__ sig,
    const float* __restrict__ skip, float* __restrict__ x)
{
    __shared__ float sred[32];
    int row = blockIdx.x;
    const float* arow = a + (size_t)row * 768;
    int t = threadIdx.x, lane = t & 31, w = t >> 5;
    float v0 = arow[t], v1 = arow[t+256], v2 = arow[t+512];
    float s = warp_sum(v0+v1+v2);
    if(lane==0) sred[w] = s;
    __syncthreads();
    if(t < 32){ float q = (t < 8) ? sred[t] : 0.f; sred[t] = warp_sum(q); }
    __syncthreads();
    float m = sred[0] * (1.f/768.f);
    __syncthreads();
    float d0 = v0-m, d1 = v1-m, d2 = v2-m;
    float vv = warp_sum(d0*d0 + d1*d1 + d2*d2);
    if(lane==0) sred[w] = vv;
    __syncthreads();
    if(t < 32){ float q = (t < 8) ? sred[t] : 0.f; sred[t] = warp_sum(q); }
    __syncthreads();
    float rs = rsqrtf(sred[0] * (1.f/768.f) + 1e-5f);
    size_t base = (size_t)row * 768 + t;
    x[base]      = sig[base]      * (d0*rs) + skip[base];
    x[base+256]  = sig[base+256]  * (d1*rs) + skip[base+256];
    x[base+512]  = sig[base+512]  * (d2*rs) + skip[base+512];
}

// ================= attention: block per (32-query tile, head) =================
#define SP_STRIDE 772
__global__ void __launch_bounds__(256) attn2_kernel(
    const float* __restrict__ Q, const float* __restrict__ Kx,
    const float* __restrict__ V, const float* __restrict__ pl,
    const float* __restrict__ mask, float* __restrict__ O)
{
    extern __shared__ float sm[];
    float* sQ   = sm;                          // 32*49
    float* sKV  = sQ + 32*49;                  // 128*49
    float* sP   = sKV + 128*49;                // 32*772
    float* sSum = sP + 32*SP_STRIDE;           // 32

    const int qt = blockIdx.x, h = blockIdx.y;
    const int q0 = qt * 32;
    const int tid = threadIdx.x;
    const float scale = rsqrtf(48.f);

    for(int i = tid; i < 32*48; i += 256){
        int q = i / 48, d = i % 48;
        sQ[q*49 + d] = Q[(size_t)(q0+q)*768 + h*48 + d];
    }

    const int qa = (tid & 7) * 4;
    const int kaa = (tid >> 3) * 4;
    for(int kt = 0; kt < 6; kt++){
        __syncthreads();
        for(int i = tid; i < 128*48; i += 256){
            int k = i / 48, d = i % 48;
            sKV[k*49 + d] = Kx[(size_t)(kt*128 + k)*768 + h*48 + d];
        }
        __syncthreads();
        float s[4][4];
        #pragma unroll
        for(int i=0;i<4;i++){ s[i][0]=0.f; s[i][1]=0.f; s[i][2]=0.f; s[i][3]=0.f; }
        #pragma unroll 4
        for(int d = 0; d < 48; d++){
            float qv[4], kv[4];
            #pragma unroll
            for(int i=0;i<4;i++) qv[i] = sQ[(qa+i)*49 + d];
            #pragma unroll
            for(int j=0;j<4;j++) kv[j] = sKV[(kaa+j)*49 + d];
            #pragma unroll
            for(int i=0;i<4;i++)
                #pragma unroll
                for(int j=0;j<4;j++) s[i][j] += qv[i]*kv[j];
        }
        int kg = kt*128 + kaa;
        float4 mk = *(const float4*)(mask + kg);
        float bb[4] = {1e9f*(mk.x-1.f), 1e9f*(mk.y-1.f), 1e9f*(mk.z-1.f), 1e9f*(mk.w-1.f)};
        #pragma unroll
        for(int i=0;i<4;i++){
            float4 plv = *(const float4*)(pl + ((size_t)h*768 + q0+qa+i)*768 + kg);
            float* prow = sP + (qa+i)*SP_STRIDE + kg;
            prow[0] = s[i][0]*scale + plv.x + bb[0];
            prow[1] = s[i][1]*scale + plv.y + bb[1];
            prow[2] = s[i][2]*scale + plv.z + bb[2];
            prow[3] = s[i][3]*scale + plv.w + bb[3];
        }
    }
    __syncthreads();

    {
        int warp = tid >> 5, lane = tid & 31;
        for(int r = warp*4; r < warp*4 + 4; r++){
            float* row = sP + r*SP_STRIDE;
            float mx = -1e30f;
            for(int k = lane; k < 768; k += 32) mx = fmaxf(mx, row[k]);
            mx = warp_max(mx);
            float sum = 0.f;
            for(int k = lane; k < 768; k += 32){
                float e = __expf(row[k] - mx);
                row[k] = e;
                sum += e;
            }
            sum = warp_sum(sum);
            if(lane == 0) sSum[r] = sum;
        }
    }
    __syncthreads();

    const int g  = tid >> 7;
    const int tt = tid & 127;
    const int q  = (tt >> 3) * 2;
    const int d0 = (tt & 7) * 6;
    float oa[2][6];
    #pragma unroll
    for(int j=0;j<6;j++){ oa[0][j]=0.f; oa[1][j]=0.f; }

    for(int kt = 0; kt < 6; kt++){
        __syncthreads();
        for(int i = tid; i < 128*48; i += 256){
            int k = i / 48, d = i % 48;
            sKV[k*49 + d] = V[(size_t)(kt*128 + k)*768 + h*48 + d];
        }
        __syncthreads();
        const int kbase = kt*128 + g*64;
        const float* p0r = sP + q*SP_STRIDE + kbase;
        const float* p1r = sP + (q+1)*SP_STRIDE + kbase;
        const float* vb  = sKV + (g*64)*49 + d0;
        #pragma unroll 4
        for(int kk = 0; kk < 64; kk++){
            float p0 = p0r[kk], p1 = p1r[kk];
            const float* vr = vb + kk*49;
            #pragma unroll
            for(int j=0;j<6;j++){
                float v = vr[j];
                oa[0][j] += p0 * v;
                oa[1][j] += p1 * v;
            }
        }
    }
    __syncthreads();
    if(g == 1){
        #pragma unroll
        for(int j=0;j<6;j++){ sP[tt*12 + j] = oa[0][j]; sP[tt*12 + 6 + j] = oa[1][j]; }
    }
    __syncthreads();
    if(g == 0){
        float inv0 = 1.f / sSum[q], inv1 = 1.f / sSum[q+1];
        #pragma unroll
        for(int j=0;j<6;j++){
            float o0 = (oa[0][j] + sP[tt*12 + j])     * inv0;
            float o1 = (oa[1][j] + sP[tt*12 + 6 + j]) * inv1;
            O[(size_t)(q0+q  )*768 + h*48 + d0 + j] = o0;
            O[(size_t)(q0+q+1)*768 + h*48 + d0 + j] = o1;
        }
    }
}

// ---------------- GLU ----------------
__global__ void glu_kernel(const float* __restrict__ u, float* __restrict__ c){
    int i = blockIdx.x * blockDim.x + threadIdx.x;
    if(i >= 768*1536) return;
    int row = i / 1536, col = i % 1536;
    float a = u[(size_t)row*3072 + col];
    float b = u[(size_t)row*3072 + 1536 + col];
    c[i] = a * sigf(a) * b;
}

// ---------------- host-side GEMM launcher ----------------
static void gemm2(const float* A, const uint32_t* Bt, float* C, int M, int N, int K,
                  const float* amean, const float* arstd, const float* amul,
                  const float* bias, int sig, const float* egate, int acc, int transc,
                  int batch, long sBt, long sC, long sBias,
                  const float* bias3 = 0, int multi = 0)
{
    dim3 g(M/64, N/64, batch);
    gemm2_kernel<<<g, 128>>>(A, Bt, C, M, N, K, amean, arstd, amul,
                             bias, sig, egate, acc, transc,
                             sBt, sC, sBias, bias3, multi);
}

extern "C" void kernel_launch(void* const* d_in, const int* in_sizes, int n_in,
                              void* d_out, int out_size)
{
    const float* act   = (const float*)d_in[0];
    const float* mask  = (const float*)d_in[1];
    const float* sc    = (const float*)d_in[2];
    const float* pc    = (const float*)d_in[3];
    const float* a_cln = (const float*)d_in[4];
    const float* a_csw = (const float*)d_in[5];
    const float* a_csb = (const float*)d_in[6];
    const float* a_cbw = (const float*)d_in[7];
    const float* qw    = (const float*)d_in[8];
    const float* qb    = (const float*)d_in[9];
    const float* kw    = (const float*)d_in[10];
    const float* vw    = (const float*)d_in[11];
    const float* gw    = (const float*)d_in[12];
    const float* gb    = (const float*)d_in[13];
    const float* ow    = (const float*)d_in[14];
    const float* a_azw = (const float*)d_in[15];
    const float* a_azb = (const float*)d_in[16];
    const float* f_cln = (const float*)d_in[17];
    const float* f_csw = (const float*)d_in[18];
    const float* f_csb = (const float*)d_in[19];
    const float* f_cbw = (const float*)d_in[20];
    const float* t1    = (const float*)d_in[21];
    const float* t2    = (const float*)d_in[22];
    const float* f_azw = (const float*)d_in[23];
    const float* f_azb = (const float*)d_in[24];
    const float* plsc  = (const float*)d_in[25];
    const float* pw    = (const float*)d_in[26];
    float* out = (float*)d_out;

    float *pl, *pm, *pr, *scm, *scr;
    float *sA, *kA, *zA, *sF, *kF, *zF;
    float *xb, *qkvg, *atB, *uB, *cB;
    uint32_t* WB;
    cudaGetSymbolAddress((void**)&pl,   g_pl);
    cudaGetSymbolAddress((void**)&WB,   g_wbf);
    cudaGetSymbolAddress((void**)&pm,   g_pmean);
    cudaGetSymbolAddress((void**)&pr,   g_prstd);
    cudaGetSymbolAddress((void**)&scm,  g_scmean);
    cudaGetSymbolAddress((void**)&scr,  g_scrstd);
    cudaGetSymbolAddress((void**)&sA,   g_sig_attn);
    cudaGetSymbolAddress((void**)&kA,   g_skip_attn);
    cudaGetSymbolAddress((void**)&zA,   g_az_attn);
    cudaGetSymbolAddress((void**)&sF,   g_sig_ffw);
    cudaGetSymbolAddress((void**)&kF,   g_skip_ffw);
    cudaGetSymbolAddress((void**)&zF,   g_az_ffw);
    cudaGetSymbolAddress((void**)&xb,   g_x);
    cudaGetSymbolAddress((void**)&qkvg, g_qkvg);
    cudaGetSymbolAddress((void**)&atB,  g_attn);
    cudaGetSymbolAddress((void**)&uB,   g_u);
    cudaGetSymbolAddress((void**)&cB,   g_c);

    static const int att_smem = (32*49 + 128*49 + 32*SP_STRIDE + 64) * 4;
    cudaFuncSetAttribute(attn2_kernel, cudaFuncAttributeMaxDynamicSharedMemorySize, att_smem);

    cudaMemcpyAsync(out, act, (size_t)NC * sizeof(float), cudaMemcpyDeviceToDevice, 0);

    // ---- weight pre-conversion to pre-tiled bf16 (cln/plsc scales folded) ----
    conv_w_kernel<<<dim3(1152,1,8),256>>>(qw, 0, WB+OFF_QW, 768, 768, (long)NC, 0);
    conv_w_kernel<<<dim3(1152,1,8),256>>>(kw, 0, WB+OFF_KW, 768, 768, (long)NC, 0);
    conv_w_kernel<<<dim3(1152,1,8),256>>>(vw, 0, WB+OFF_VW, 768, 768, (long)NC, 0);
    conv_w_kernel<<<dim3(1152,1,8),256>>>(gw, 0, WB+OFF_GW, 768, 768, (long)NC, 0);
    conv_w_kernel<<<dim3(1152,1,8),256>>>(ow, 0, WB+OFF_OW, 768, 768, (long)NC, 0);
    conv_w_kernel<<<dim3(4608,1,8),256>>>(t1, 0, WB+OFF_T1, 768, 3072, (long)CD*2*FD, 0);
    conv_w_kernel<<<dim3(2304,1,8),256>>>(t2, 0, WB+OFF_T2, 1536, 768, (long)FD*CD, 0);
    conv_w_kernel<<<dim3(576,1,8),256>>>(a_csw, a_cln, WB+OFF_ACSW, 384, 768, (long)CSD*CD, CSD);
    conv_w_kernel<<<dim3(576,1,8),256>>>(a_cbw, a_cln, WB+OFF_ACBW, 384, 768, (long)CSD*CD, CSD);
    conv_w_kernel<<<dim3(576,1,8),256>>>(a_azw, 0,     WB+OFF_AAZW, 384, 768, (long)CSD*CD, 0);
    conv_w_kernel<<<dim3(576,1,8),256>>>(f_csw, f_cln, WB+OFF_FCSW, 384, 768, (long)CSD*CD, CSD);
    conv_w_kernel<<<dim3(576,1,8),256>>>(f_cbw, f_cln, WB+OFF_FCBW, 384, 768, (long)CSD*CD, CSD);
    conv_w_kernel<<<dim3(576,1,8),256>>>(f_azw, 0,     WB+OFF_FAZW, 384, 768, (long)CSD*CD, 0);
    conv_pw_kernel<<<32,256>>>(pw, plsc, WB+OFF_PW);

    rowstats_kernel<<<(NT + 7) / 8, 256>>>(sc, scm, scr, NT, CSD);
    rowstats_kernel<<<(NN + 7) / 8, 256>>>(pc, pm, pr, NN, CPD);

    // pair logits: LN(pair_cond) @ (plsc-scaled W) -> g_pl (coalesced transposed write)
    gemm2(pc, WB+OFF_PW, pl, NN, 128, 128, pm, pr, 0, 0, 0, 0, 0, 1, 1, 0, 0, 0);

    // conditioning, batched across layers via gridDim.z (cln folded into weights)
    gemm2(sc, WB+OFF_ACSW, sA, NT, CD, CSD, scm, scr, 0, a_csb, 1, 0, 0, 0,
          LL, 147456, NC, CD);
    gemm2(sc, WB+OFF_ACBW, kA, NT, CD, CSD, scm, scr, 0, 0, 0, 0, 0, 0,
          LL, 147456, NC, 0);
    gemm2(sc, WB+OFF_AAZW, zA, NT, CD, CSD, 0, 0, 0, a_azb, 1, 0, 0, 0,
          LL, 147456, NC, CD);
    gemm2(sc, WB+OFF_FCSW, sF, NT, CD, CSD, scm, scr, 0, f_csb, 1, 0, 0, 0,
          LL, 147456, NC, CD);
    gemm2(sc, WB+OFF_FCBW, kF, NT, CD, CSD, scm, scr, 0, 0, 0, 0, 0, 0,
          LL, 147456, NC, 0);
    gemm2(sc, WB+OFF_FAZW, zF, NT, CD, CSD, 0, 0, 0, f_azb, 1, 0, 0, 0,
          LL, 147456, NC, CD);

    for(int l = 0; l < LL; l++){
        adaln_apply_kernel<<<NT, 256>>>(out, sA + (size_t)l*NC, kA + (size_t)l*NC, xb);

        // q,k,v,gate in ONE batched launch (z strides across the 4 weight blocks)
        gemm2(xb, WB + OFF_QW + (size_t)l*U_SQ, qkvg, NT, CD, CD, 0, 0, 0,
              qb + (size_t)l*CD, 0, 0, 0, 0,
              4, 2359296, NC, 0, gb + (size_t)l*CD, /*multi=*/1);

        attn2_kernel<<<dim3(NT/32, HH), 256, att_smem>>>(
            qkvg, qkvg + NC, qkvg + 2*NC, pl + (size_t)l*16*NC, mask, atB);

        // a += sig_az_attn * ((attn*gate) @ out_w)
        gemm2(atB, WB + OFF_OW + (size_t)l*U_SQ, out, NT, CD, CD, 0, 0,
              qkvg + 3*NC, 0, 0, zA + (size_t)l*NC, 1, 0, 1, 0, 0, 0);

        adaln_apply_kernel<<<NT, 256>>>(out, sF + (size_t)l*NC, kF + (size_t)l*NC, xb);

        gemm2(xb, WB + OFF_T1 + (size_t)l*1179648, uB, NT, 2*FD, CD, 0, 0, 0,
              0, 0, 0, 0, 0, 1, 0, 0, 0);
        glu_kernel<<<(768*1536)/256, 256>>>(uB, cB);

        // a += sig_az_ffw * (c @ t2)
        gemm2(cB, WB + OFF_T2 + (size_t)l*589824, out, NT, CD, FD, 0, 0, 0,
              0, 0, zF + (size_t)l*NC, 1, 0, 1, 0, 0, 0);
    }
}

// round 17
// speedup vs baseline: 3.3014x; 1.2788x over previous
#include <cuda_runtime.h>
#include <cuda_fp16.h>
#include <math.h>
#include <stdint.h>

// Problem constants
#define NT 768          // tokens
#define CD 768          // channels
#define CSD 384         // single_cond channels
#define CPD 128         // pair channels
#define HH 16           // heads
#define KDIM 48         // head dim
#define FD 1536         // ffn intermediate
#define LL 8            // layers
#define NC (768*768)
#define NN (768*768)    // pair rows

// ---- pre-tiled bf16 weight buffer offsets (uint32 units; each u32 = bf16x2) ----
#define U_SQ   294912            // 768*768/2
#define OFF_QW   0
#define OFF_KW   2359296
#define OFF_VW   4718592
#define OFF_GW   7077888
#define OFF_OW   9437184
#define OFF_T1   11796480
#define OFF_T2   21233664
#define OFF_ACSW 25952256
#define OFF_ACBW 27131904
#define OFF_AAZW 28311552
#define OFF_FCSW 29491200
#define OFF_FCBW 30670848
#define OFF_FAZW 31850496
#define OFF_PW   33030144
#define WBF_TOTAL 33038336

// ---------------- static device scratch ----------------
__device__ float g_pl[LL*16*768*768];        // reused as fp16x2 (u32) pair logits
__device__ uint32_t g_wbf[WBF_TOTAL];        // pre-tiled bf16 weights
__device__ uint32_t g_qkv16[3*294912];       // q16 | k16 | vT16 (bf16x2)
__device__ float g_pmean[NN];
__device__ float g_prstd[NN];
__device__ float g_scmean[NT];
__device__ float g_scrstd[NT];
__device__ float g_sig_attn[LL*NC];
__device__ float g_skip_attn[LL*NC];
__device__ float g_az_attn[LL*NC];
__device__ float g_sig_ffw[LL*NC];
__device__ float g_skip_ffw[LL*NC];
__device__ float g_az_ffw[LL*NC];
__device__ float g_x[NC];
__device__ float g_qkvg[4*NC];               // z=3 gate (f32) lives at +3*NC
__device__ float g_attn[NC];
__device__ float g_u[768*3072];
__device__ float g_c[768*1536];

__device__ __forceinline__ float sigf(float x){ return 1.0f/(1.0f+__expf(-x)); }

__device__ __forceinline__ uint32_t pkbf(float lo, float hi){
    uint32_t r; asm("cvt.rn.bf16x2.f32 %0, %1, %2;" : "=r"(r) : "f"(hi), "f"(lo));
    return r;
}
__device__ __forceinline__ uint32_t pkhf(float lo, float hi){
    uint32_t r; asm("cvt.rn.f16x2.f32 %0, %1, %2;" : "=r"(r) : "f"(hi), "f"(lo));
    return r;
}

__device__ __forceinline__ float warp_sum(float v){
    #pragma unroll
    for(int o=16;o;o>>=1) v += __shfl_xor_sync(0xffffffffu, v, o);
    return v;
}
__device__ __forceinline__ float warp_max(float v){
    #pragma unroll
    for(int o=16;o;o>>=1) v = fmaxf(v, __shfl_xor_sync(0xffffffffu, v, o));
    return v;
}

// ---------------- row stats ----------------
__global__ void rowstats_kernel(const float* __restrict__ X, float* __restrict__ mean,
                                float* __restrict__ rstd, int rows, int cols){
    int row = blockIdx.x * (blockDim.x >> 5) + (threadIdx.x >> 5);
    if(row >= rows) return;
    int lane = threadIdx.x & 31;
    const float* x = X + (size_t)row * cols;
    float s = 0.f, sq = 0.f;
    for(int c = lane; c < cols; c += 32){ float v = x[c]; s += v; sq += v*v; }
    s = warp_sum(s); sq = warp_sum(sq);
    if(lane == 0){
        float m = s / cols;
        float var = sq / cols - m*m;
        if(var < 0.f) var = 0.f;
        mean[row] = m;
        rstd[row] = rsqrtf(var + 1e-5f);
    }
}

// ---------------- weight conversion: f32 [K][N] -> pre-tiled bf16 fragments ----
__global__ void conv_w_kernel(const float* __restrict__ W, const float* __restrict__ rs,
                              uint32_t* __restrict__ out, int K, int N,
                              long sW, long sRS){
    int z = blockIdx.z;
    const float* Wp = W + (size_t)z * sW;
    const float* rp = rs ? rs + (size_t)z * sRS : (const float*)0;
    long total = (long)K * N / 2;
    long gid = (long)blockIdx.x * 256 + threadIdx.x;
    if(gid >= total) return;
    int k2 = (int)(gid / N), n = (int)(gid - (long)k2 * N);
    int k = k2 * 2;
    float lo = Wp[(size_t)k*N + n], hi = Wp[(size_t)(k+1)*N + n];
    if(rp){ lo *= rp[k]; hi *= rp[k+1]; }
    int kt = k >> 5, kk = k & 31, s = kk >> 4, p = (kk & 15) >> 1;
    int ntl = n >> 6, nn = n & 63, nblk = nn >> 3;
    int lane = (nn & 7) * 4 + (p & 3), reg = p >> 2;
    int KT = K >> 5;
    size_t idx = (size_t)(ntl * KT + kt) * 1024 + s*512 + nblk*64 + lane*2 + reg;
    out[(size_t)z * (size_t)(K*N/2) + idx] = pkbf(lo, hi);
}

__global__ void conv_pw_kernel(const float* __restrict__ pw,
                               const float* __restrict__ plsc,
                               uint32_t* __restrict__ out){
    int gid = blockIdx.x * 256 + threadIdx.x;
    if(gid >= 8192) return;
    int k2 = gid >> 7, n = gid & 127;
    int k = k2 * 2;
    int sb = n >> 6, j = n & 63;
    float lo = pw[sb*8192 + k*64 + j]     * plsc[k];
    float hi = pw[sb*8192 + (k+1)*64 + j] * plsc[k+1];
    int kt = k >> 5, kk = k & 31, s = kk >> 4, p = (kk & 15) >> 1;
    int ntl = n >> 6, nn = n & 63, nblk = nn >> 3;
    int lane = (nn & 7) * 4 + (p & 3), reg = p >> 2;
    size_t idx = (size_t)(ntl * 4 + kt) * 1024 + s*512 + nblk*64 + lane*2 + reg;
    out[idx] = pkbf(lo, hi);
}

// ================= BF16 tensor-core GEMM v2 =================
// multi mode (QKVG): z=0 q -> bf16 [tok][n/2] (+qb); z=1 k -> bf16;
//                    z=2 v -> bf16 TRANSPOSED [n][tok/2]; z=3 gate -> f32 sigmoid.
// do_transc: 0 none, 1 f32 transposed, 2 fp16 transposed (pair logits).
__global__ void __launch_bounds__(128) gemm2_kernel(
    const float* __restrict__ A, const uint32_t* __restrict__ Bt, float* __restrict__ C,
    int M, int N, int K,
    const float* __restrict__ amean, const float* __restrict__ arstd,
    const float* __restrict__ amul,
    const float* __restrict__ bias, int do_sig,
    const float* __restrict__ egate, int do_acc, int do_transc,
    long sBt, long sC, long sBias,
    const float* __restrict__ bias3, int multi, uint32_t* __restrict__ C16)
{
    __shared__ __align__(16) char sraw[17408];
    uint32_t* As2 = (uint32_t*)sraw;
    uint32_t* Bs2 = (uint32_t*)(sraw + 4096);

    const int z = blockIdx.z;
    const uint32_t* Bp = Bt + (size_t)z * sBt;
    const float* biasp;
    int sig;
    if(multi){
        biasp = (z==0) ? bias : (z==3 ? bias3 : (const float*)0);
        sig   = (z==3);
    } else {
        biasp = bias ? bias + (size_t)z * sBias : (const float*)0;
        sig   = do_sig;
    }
    float* Cp = C + (size_t)z * sC;

    const int tid  = threadIdx.x;
    const int m0   = blockIdx.x * 64;
    const int nt   = blockIdx.y;
    const int n0   = nt * 64;
    const int KT   = K >> 5;
    const int warp = tid >> 5, lane = tid & 31;
    const int wm   = warp >> 1, wn = warp & 1;
    const int lr   = lane >> 2, lc = lane & 3;

    const int arow = tid & 63;
    const int ka   = (tid >> 6) * 8;
    float am = 0.f, ar = 1.f;
    if(amean){ am = amean[m0 + arow]; ar = arstd[m0 + arow]; }
    const float* Aptr = A + (size_t)(m0 + arow) * K;
    const float* Mptr = amul ? amul + (size_t)(m0 + arow) * K : (const float*)0;
    const int aLaneB = (arow & 7) * 4;
    const int aReg   = ((ka >> 3) << 1) + ((arow >> 3) & 1);
    const int aMblk  = arow >> 4;

    const uint32_t* Btile = Bp + (size_t)nt * KT * 1024;

    float aPf[16];
    uint4 bPf0, bPf1;
    float acc[2][4][4];
    #pragma unroll
    for(int t=0;t<2;t++)
        #pragma unroll
        for(int j=0;j<4;j++){ acc[t][j][0]=0.f; acc[t][j][1]=0.f; acc[t][j][2]=0.f; acc[t][j][3]=0.f; }

    #pragma unroll
    for(int s2=0;s2<2;s2++){
        *(float4*)&aPf[s2*8]   = *(const float4*)(Aptr + s2*16 + ka);
        *(float4*)&aPf[s2*8+4] = *(const float4*)(Aptr + s2*16 + ka + 4);
    }
    bPf0 = *(const uint4*)(Btile + tid*8);
    bPf1 = *(const uint4*)(Btile + tid*8 + 4);

    for(int kt = 0; kt < KT; kt++){
        #pragma unroll
        for(int s2=0;s2<2;s2++){
            float av[8];
            #pragma unroll
            for(int i=0;i<8;i++) av[i] = aPf[s2*8+i];
            if(amean){
                #pragma unroll
                for(int i=0;i<8;i++) av[i] = (av[i]-am)*ar;
            }
            if(Mptr){
                const int kg = kt*32 + s2*16 + ka;
                float4 m0v = *(const float4*)(Mptr + kg);
                float4 m1v = *(const float4*)(Mptr + kg + 4);
                av[0]*=m0v.x; av[1]*=m0v.y; av[2]*=m0v.z; av[3]*=m0v.w;
                av[4]*=m1v.x; av[5]*=m1v.y; av[6]*=m1v.z; av[7]*=m1v.w;
            }
            #pragma unroll
            for(int i=0;i<4;i++)
                As2[s2*512 + aMblk*128 + (aLaneB+i)*4 + aReg] = pkbf(av[2*i], av[2*i+1]);
        }
        *(uint4*)&Bs2[tid*8]     = bPf0;
        *(uint4*)&Bs2[tid*8 + 4] = bPf1;
        __syncthreads();

        if(kt+1 < KT){
            const float* An = Aptr + (kt+1)*32;
            #pragma unroll
            for(int s2=0;s2<2;s2++){
                *(float4*)&aPf[s2*8]   = *(const float4*)(An + s2*16 + ka);
                *(float4*)&aPf[s2*8+4] = *(const float4*)(An + s2*16 + ka + 4);
            }
            const uint32_t* Bn = Btile + (size_t)(kt+1)*1024;
            bPf0 = *(const uint4*)(Bn + tid*8);
            bPf1 = *(const uint4*)(Bn + tid*8 + 4);
        }

        #pragma unroll
        for(int s=0;s<2;s++){
            uint32_t af[2][4];
            #pragma unroll
            for(int t=0;t<2;t++){
                uint4 v = *(const uint4*)&As2[s*512 + (wm*2+t)*128 + lane*4];
                af[t][0]=v.x; af[t][1]=v.y; af[t][2]=v.z; af[t][3]=v.w;
            }
            #pragma unroll
            for(int j=0;j<4;j++){
                uint2 bv = *(const uint2*)&Bs2[s*512 + (wn*4+j)*64 + lane*2];
                #pragma unroll
                for(int t=0;t<2;t++){
                    asm volatile(
                        "mma.sync.aligned.m16n8k16.row.col.f32.bf16.bf16.f32 "
                        "{%0,%1,%2,%3}, {%4,%5,%6,%7}, {%8,%9}, {%0,%1,%2,%3};"
                        : "+f"(acc[t][j][0]), "+f"(acc[t][j][1]),
                          "+f"(acc[t][j][2]), "+f"(acc[t][j][3])
                        : "r"(af[t][0]), "r"(af[t][1]), "r"(af[t][2]), "r"(af[t][3]),
                          "r"(bv.x), "r"(bv.y));
                }
            }
        }
        __syncthreads();
    }

    // ---- epilogue ----
    if(multi && z < 2){
        // bf16 direct write [row][col/2]
        uint32_t* Op = C16 + (size_t)z * (size_t)(NC/2);
        #pragma unroll
        for(int t=0;t<2;t++){
            #pragma unroll
            for(int j=0;j<4;j++){
                const int rr = m0 + wm*32 + t*16 + lr;
                const int cc = n0 + wn*32 + j*8 + 2*lc;
                float2 r0 = make_float2(acc[t][j][0], acc[t][j][1]);
                float2 r1 = make_float2(acc[t][j][2], acc[t][j][3]);
                if(biasp){ float2 bv = *(const float2*)(biasp + cc);
                           r0.x+=bv.x; r0.y+=bv.y; r1.x+=bv.x; r1.y+=bv.y; }
                Op[(size_t)rr*384 + (cc>>1)]     = pkbf(r0.x, r0.y);
                Op[(size_t)(rr+8)*384 + (cc>>1)] = pkbf(r1.x, r1.y);
            }
        }
    } else if(multi && z == 2){
        // bf16 transposed write [col][row/2] via smem staging
        float (*sCt)[68] = (float(*)[68])sraw;
        #pragma unroll
        for(int t=0;t<2;t++){
            #pragma unroll
            for(int j=0;j<4;j++){
                const int rr = wm*32 + t*16 + lr;
                const int cc = wn*32 + j*8 + 2*lc;
                sCt[cc  ][rr  ] = acc[t][j][0];
                sCt[cc+1][rr  ] = acc[t][j][1];
                sCt[cc  ][rr+8] = acc[t][j][2];
                sCt[cc+1][rr+8] = acc[t][j][3];
            }
        }
        __syncthreads();
        uint32_t* Op = C16 + 2*(size_t)(NC/2);
        #pragma unroll
        for(int it=0; it<8; it++){
            int idx = tid + it*128;
            int n = idx >> 4, mq = (idx & 15) * 4;
            float4 v = *(const float4*)&sCt[n][mq];
            uint2 o; o.x = pkbf(v.x, v.y); o.y = pkbf(v.z, v.w);
            *(uint2*)&Op[(size_t)(n0+n)*384 + ((m0+mq)>>1)] = o;
        }
    } else if(do_transc == 1){
        float (*sCt)[68] = (float(*)[68])sraw;
        #pragma unroll
        for(int t=0;t<2;t++){
            #pragma unroll
            for(int j=0;j<4;j++){
                const int rr = wm*32 + t*16 + lr;
                const int cc = wn*32 + j*8 + 2*lc;
                sCt[cc  ][rr  ] = acc[t][j][0];
                sCt[cc+1][rr  ] = acc[t][j][1];
                sCt[cc  ][rr+8] = acc[t][j][2];
                sCt[cc+1][rr+8] = acc[t][j][3];
            }
        }
        __syncthreads();
        #pragma unroll
        for(int it=0; it<8; it++){
            int idx = tid + it*128;
            int n = idx >> 4, mq = (idx & 15) * 4;
            float4 v = *(const float4*)&sCt[n][mq];
            *(float4*)(Cp + (size_t)(n0+n)*M + m0 + mq) = v;
        }
    } else if(do_transc == 2){
        // fp16 transposed (pair logits)
        float (*sCt)[68] = (float(*)[68])sraw;
        #pragma unroll
        for(int t=0;t<2;t++){
            #pragma unroll
            for(int j=0;j<4;j++){
                const int rr = wm*32 + t*16 + lr;
                const int cc = wn*32 + j*8 + 2*lc;
                sCt[cc  ][rr  ] = acc[t][j][0];
                sCt[cc+1][rr  ] = acc[t][j][1];
                sCt[cc  ][rr+8] = acc[t][j][2];
                sCt[cc+1][rr+8] = acc[t][j][3];
            }
        }
        __syncthreads();
        uint32_t* Op = (uint32_t*)Cp;
        const size_t Mh = (size_t)M >> 1;
        #pragma unroll
        for(int it=0; it<8; it++){
            int idx = tid + it*128;
            int n = idx >> 4, mq = (idx & 15) * 4;
            float4 v = *(const float4*)&sCt[n][mq];
            uint2 o; o.x = pkhf(v.x, v.y); o.y = pkhf(v.z, v.w);
            *(uint2*)&Op[(size_t)(n0+n)*Mh + ((m0+mq)>>1)] = o;
        }
    } else {
        #pragma unroll
        for(int t=0;t<2;t++){
            #pragma unroll
            for(int j=0;j<4;j++){
                const int rr = m0 + wm*32 + t*16 + lr;
                const int cc = n0 + wn*32 + j*8 + 2*lc;
                float2 r0 = make_float2(acc[t][j][0], acc[t][j][1]);
                float2 r1 = make_float2(acc[t][j][2], acc[t][j][3]);
                if(biasp){ float2 bv = *(const float2*)(biasp + cc);
                           r0.x+=bv.x; r0.y+=bv.y; r1.x+=bv.x; r1.y+=bv.y; }
                if(sig){ r0.x=sigf(r0.x); r0.y=sigf(r0.y); r1.x=sigf(r1.x); r1.y=sigf(r1.y); }
                if(egate){
                    float2 g0 = *(const float2*)(egate + (size_t)rr*N + cc);
                    float2 g1 = *(const float2*)(egate + (size_t)(rr+8)*N + cc);
                    r0.x*=g0.x; r0.y*=g0.y; r1.x*=g1.x; r1.y*=g1.y;
                }
                float* cp0 = Cp + (size_t)rr*N + cc;
                float* cp1 = Cp + (size_t)(rr+8)*N + cc;
                if(do_acc){
                    float2 c0 = *(const float2*)cp0; r0.x+=c0.x; r0.y+=c0.y;
                    float2 c1 = *(const float2*)cp1; r1.x+=c1.x; r1.y+=c1.y;
                }
                *(float2*)cp0 = r0;
                *(float2*)cp1 = r1;
            }
        }
    }
}

// ---------------- fused adaLN apply ----------------
__global__ void __launch_bounds__(256) adaln_apply_kernel(
    const float* __restrict__ a, const float* __restrict__ sig,
    const float* __restrict__ skip, float* __restrict__ x)
{
    __shared__ float sred[32];
    int row = blockIdx.x;
    const float* arow = a + (size_t)row * 768;
    int t = threadIdx.x, lane = t & 31, w = t >> 5;
    float v0 = arow[t], v1 = arow[t+256], v2 = arow[t+512];
    float s = warp_sum(v0+v1+v2);
    if(lane==0) sred[w] = s;
    __syncthreads();
    if(t < 32){ float q = (t < 8) ? sred[t] : 0.f; sred[t] = warp_sum(q); }
    __syncthreads();
    float m = sred[0] * (1.f/768.f);
    __syncthreads();
    float d0 = v0-m, d1 = v1-m, d2 = v2-m;
    float vv = warp_sum(d0*d0 + d1*d1 + d2*d2);
    if(lane==0) sred[w] = vv;
    __syncthreads();
    if(t < 32){ float q = (t < 8) ? sred[t] : 0.f; sred[t] = warp_sum(q); }
    __syncthreads();
    float rs = rsqrtf(sred[0] * (1.f/768.f) + 1e-5f);
    size_t base = (size_t)row * 768 + t;
    x[base]      = sig[base]      * (d0*rs) + skip[base];
    x[base+256]  = sig[base+256]  * (d1*rs) + skip[base+256];
    x[base+512]  = sig[base+512]  * (d2*rs) + skip[base+512];
}

// ================= attention v3: tensor-core, block per (32q-tile, head) ======
// smem: sQ[32][36]u32, sK[128][36]u32, sVt[48][388]u32, sP[32][776]f32, sSum[32]
#define ATT_SMEM ((32*36 + 128*36 + 48*388)*4 + (32*776 + 32)*4)
__global__ void __launch_bounds__(256) attn3_kernel(
    const uint32_t* __restrict__ Q16, const uint32_t* __restrict__ K16,
    const uint32_t* __restrict__ VT16, const uint32_t* __restrict__ PL16,
    const float* __restrict__ mask, float* __restrict__ O)
{
    extern __shared__ char smraw[];
    uint32_t* sQ  = (uint32_t*)smraw;            // [32][36]
    uint32_t* sK  = sQ + 32*36;                  // [128][36]
    uint32_t* sVt = sK + 128*36;                 // [48][388]
    float* sP   = (float*)(sVt + 48*388);        // [32][776]
    float* sSum = sP + 32*776;                   // [32]

    const int qt = blockIdx.x, h = blockIdx.y;
    const int q0 = qt*32;
    const int tid = threadIdx.x;
    const int w = tid>>5, lane = tid&31;
    const int lr = lane>>2, lc = lane&3;
    const float scale = rsqrtf(48.f);
    const uint32_t* plh = PL16 + (size_t)h * 294912;

    // stage Q (bf16x2)
    for(int i = tid; i < 32*24; i += 256){
        int q = i/24, j = i%24;
        sQ[q*36 + j] = Q16[(size_t)(q0+q)*384 + h*24 + j];
    }
    __syncthreads();

    // Q fragments (same for every warp): [mtile][kstep][4]
    uint32_t aF[2][3][4];
    #pragma unroll
    for(int t=0;t<2;t++)
        #pragma unroll
        for(int ks=0;ks<3;ks++){
            aF[t][ks][0] = sQ[(t*16+lr  )*36 + ks*8+lc  ];
            aF[t][ks][1] = sQ[(t*16+lr+8)*36 + ks*8+lc  ];
            aF[t][ks][2] = sQ[(t*16+lr  )*36 + ks*8+lc+4];
            aF[t][ks][3] = sQ[(t*16+lr+8)*36 + ks*8+lc+4];
        }

    // ---------- pass 1: S = QK^T*scale + pl + maskbias ----------
    for(int kt = 0; kt < 6; kt++){
        __syncthreads();
        for(int i = tid; i < 128*24; i += 256){
            int k = i/24, j = i%24;
            sK[k*36 + j] = K16[(size_t)(kt*128+k)*384 + h*24 + j];
        }
        __syncthreads();
        float acc[2][2][4];
        #pragma unroll
        for(int t=0;t<2;t++)
            #pragma unroll
            for(int nb=0;nb<2;nb++){ acc[t][nb][0]=0.f; acc[t][nb][1]=0.f;
                                     acc[t][nb][2]=0.f; acc[t][nb][3]=0.f; }
        #pragma unroll
        for(int nb=0; nb<2; nb++){
            const int kb = (w*2+nb)*8;
            #pragma unroll
            for(int ks=0; ks<3; ks++){
                uint32_t b0 = sK[(kb+lr)*36 + ks*8+lc  ];
                uint32_t b1 = sK[(kb+lr)*36 + ks*8+lc+4];
                #pragma unroll
                for(int t=0;t<2;t++){
                    asm volatile(
                        "mma.sync.aligned.m16n8k16.row.col.f32.bf16.bf16.f32 "
                        "{%0,%1,%2,%3}, {%4,%5,%6,%7}, {%8,%9}, {%0,%1,%2,%3};"
                        : "+f"(acc[t][nb][0]), "+f"(acc[t][nb][1]),
                          "+f"(acc[t][nb][2]), "+f"(acc[t][nb][3])
                        : "r"(aF[t][ks][0]), "r"(aF[t][ks][1]),
                          "r"(aF[t][ks][2]), "r"(aF[t][ks][3]),
                          "r"(b0), "r"(b1));
                }
            }
        }
        #pragma unroll
        for(int t=0;t<2;t++){
            #pragma unroll
            for(int nb=0;nb<2;nb++){
                const int row = t*16+lr;
                const int col = kt*128 + (w*2+nb)*8 + 2*lc;
                float2 mk = *(const float2*)(mask + col);
                float bb0 = 1e9f*(mk.x-1.f), bb1 = 1e9f*(mk.y-1.f);
                uint32_t pv0 = plh[(size_t)(q0+row  )*384 + (col>>1)];
                uint32_t pv1 = plh[(size_t)(q0+row+8)*384 + (col>>1)];
                float2 p0 = __half22float2(*(__half2*)&pv0);
                float2 p1 = __half22float2(*(__half2*)&pv1);
                *(float2*)&sP[row*776 + col] = make_float2(
                    acc[t][nb][0]*scale + p0.x + bb0,
                    acc[t][nb][1]*scale + p0.y + bb1);
                *(float2*)&sP[(row+8)*776 + col] = make_float2(
                    acc[t][nb][2]*scale + p1.x + bb0,
                    acc[t][nb][3]*scale + p1.y + bb1);
            }
        }
    }
    __syncthreads();

    // ---------- softmax (warp handles 4 rows) ----------
    for(int r = w*4; r < w*4 + 4; r++){
        float* row = sP + r*776;
        float mx = -1e30f;
        for(int k = lane; k < 768; k += 32) mx = fmaxf(mx, row[k]);
        mx = warp_max(mx);
        float sum = 0.f;
        for(int k = lane; k < 768; k += 32){
            float e = __expf(row[k] - mx);
            row[k] = e;
            sum += e;
        }
        sum = warp_sum(sum);
        if(lane == 0) sSum[r] = sum;
    }
    __syncthreads();

    // stage V^T (bf16x2, key pairs)
    for(int i = tid; i < 48*384; i += 256){
        int d = i/384, u = i%384;
        sVt[d*388 + u] = VT16[(size_t)(h*48+d)*384 + u];
    }
    __syncthreads();

    // ---------- pass 2: O = P @ V, warp w covers keys [w*96, w*96+96) ----------
    float accO[2][6][4];
    #pragma unroll
    for(int t=0;t<2;t++)
        #pragma unroll
        for(int nb=0;nb<6;nb++){ accO[t][nb][0]=0.f; accO[t][nb][1]=0.f;
                                 accO[t][nb][2]=0.f; accO[t][nb][3]=0.f; }
    const int wk0 = w*96;
    #pragma unroll
    for(int ksl=0; ksl<6; ksl++){
        const int k0 = wk0 + ksl*16;
        uint32_t a[2][4];
        #pragma unroll
        for(int t=0;t<2;t++){
            float2 v0 = *(const float2*)&sP[(t*16+lr  )*776 + k0     + 2*lc];
            float2 v1 = *(const float2*)&sP[(t*16+lr+8)*776 + k0     + 2*lc];
            float2 v2 = *(const float2*)&sP[(t*16+lr  )*776 + k0 + 8 + 2*lc];
            float2 v3 = *(const float2*)&sP[(t*16+lr+8)*776 + k0 + 8 + 2*lc];
            a[t][0]=pkbf(v0.x,v0.y); a[t][1]=pkbf(v1.x,v1.y);
            a[t][2]=pkbf(v2.x,v2.y); a[t][3]=pkbf(v3.x,v3.y);
        }
        #pragma unroll
        for(int nb=0;nb<6;nb++){
            uint32_t b0 = sVt[(nb*8+lr)*388 + (k0>>1)+lc  ];
            uint32_t b1 = sVt[(nb*8+lr)*388 + (k0>>1)+lc+4];
            #pragma unroll
            for(int t=0;t<2;t++){
                asm volatile(
                    "mma.sync.aligned.m16n8k16.row.col.f32.bf16.bf16.f32 "
                    "{%0,%1,%2,%3}, {%4,%5,%6,%7}, {%8,%9}, {%0,%1,%2,%3};"
                    : "+f"(accO[t][nb][0]), "+f"(accO[t][nb][1]),
                      "+f"(accO[t][nb][2]), "+f"(accO[t][nb][3])
                    : "r"(a[t][0]), "r"(a[t][1]), "r"(a[t][2]), "r"(a[t][3]),
                      "r"(b0), "r"(b1));
            }
        }
    }
    __syncthreads();          // all P reads done; sP reusable as reduction buffer

    #pragma unroll
    for(int t=0;t<2;t++){
        #pragma unroll
        for(int nb=0;nb<6;nb++){
            const int q = t*16+lr, d = nb*8+2*lc;
            sP[w*1536 + q*48 + d]        = accO[t][nb][0];
            sP[w*1536 + q*48 + d+1]      = accO[t][nb][1];
            sP[w*1536 + (q+8)*48 + d]    = accO[t][nb][2];
            sP[w*1536 + (q+8)*48 + d+1]  = accO[t][nb][3];
        }
    }
    __syncthreads();
    for(int o = tid; o < 1536; o += 256){
        int q = o/48, d = o%48;
        float s = 0.f;
        #pragma unroll
        for(int ww=0; ww<8; ww++) s += sP[ww*1536 + o];
        O[(size_t)(q0+q)*768 + h*48 + d] = s / sSum[q];
    }
}

// ---------------- GLU ----------------
__global__ void glu_kernel(const float* __restrict__ u, float* __restrict__ c){
    int i = blockIdx.x * blockDim.x + threadIdx.x;
    if(i >= 768*1536) return;
    int row = i / 1536, col = i % 1536;
    float a = u[(size_t)row*3072 + col];
    float b = u[(size_t)row*3072 + 1536 + col];
    c[i] = a * sigf(a) * b;
}

// ---------------- host-side GEMM launcher ----------------
static void gemm2(const float* A, const uint32_t* Bt, float* C, int M, int N, int K,
                  const float* amean, const float* arstd, const float* amul,
                  const float* bias, int sig, const float* egate, int acc, int transc,
                  int batch, long sBt, long sC, long sBias,
                  const float* bias3 = 0, int multi = 0, uint32_t* C16 = 0)
{
    dim3 g(M/64, N/64, batch);
    gemm2_kernel<<<g, 128>>>(A, Bt, C, M, N, K, amean, arstd, amul,
                             bias, sig, egate, acc, transc,
                             sBt, sC, sBias, bias3, multi, C16);
}

extern "C" void kernel_launch(void* const* d_in, const int* in_sizes, int n_in,
                              void* d_out, int out_size)
{
    const float* act   = (const float*)d_in[0];
    const float* mask  = (const float*)d_in[1];
    const float* sc    = (const float*)d_in[2];
    const float* pc    = (const float*)d_in[3];
    const float* a_cln = (const float*)d_in[4];
    const float* a_csw = (const float*)d_in[5];
    const float* a_csb = (const float*)d_in[6];
    const float* a_cbw = (const float*)d_in[7];
    const float* qw    = (const float*)d_in[8];
    const float* qb    = (const float*)d_in[9];
    const float* kw    = (const float*)d_in[10];
    const float* vw    = (const float*)d_in[11];
    const float* gw    = (const float*)d_in[12];
    const float* gb    = (const float*)d_in[13];
    const float* ow    = (const float*)d_in[14];
    const float* a_azw = (const float*)d_in[15];
    const float* a_azb = (const float*)d_in[16];
    const float* f_cln = (const float*)d_in[17];
    const float* f_csw = (const float*)d_in[18];
    const float* f_csb = (const float*)d_in[19];
    const float* f_cbw = (const float*)d_in[20];
    const float* t1    = (const float*)d_in[21];
    const float* t2    = (const float*)d_in[22];
    const float* f_azw = (const float*)d_in[23];
    const float* f_azb = (const float*)d_in[24];
    const float* plsc  = (const float*)d_in[25];
    const float* pw    = (const float*)d_in[26];
    float* out = (float*)d_out;

    float *pl, *pm, *pr, *scm, *scr;
    float *sA, *kA, *zA, *sF, *kF, *zF;
    float *xb, *qkvg, *atB, *uB, *cB;
    uint32_t *WB, *QKV16;
    cudaGetSymbolAddress((void**)&pl,    g_pl);
    cudaGetSymbolAddress((void**)&WB,    g_wbf);
    cudaGetSymbolAddress((void**)&QKV16, g_qkv16);
    cudaGetSymbolAddress((void**)&pm,    g_pmean);
    cudaGetSymbolAddress((void**)&pr,    g_prstd);
    cudaGetSymbolAddress((void**)&scm,   g_scmean);
    cudaGetSymbolAddress((void**)&scr,   g_scrstd);
    cudaGetSymbolAddress((void**)&sA,    g_sig_attn);
    cudaGetSymbolAddress((void**)&kA,    g_skip_attn);
    cudaGetSymbolAddress((void**)&zA,    g_az_attn);
    cudaGetSymbolAddress((void**)&sF,    g_sig_ffw);
    cudaGetSymbolAddress((void**)&kF,    g_skip_ffw);
    cudaGetSymbolAddress((void**)&zF,    g_az_ffw);
    cudaGetSymbolAddress((void**)&xb,    g_x);
    cudaGetSymbolAddress((void**)&qkvg,  g_qkvg);
    cudaGetSymbolAddress((void**)&atB,   g_attn);
    cudaGetSymbolAddress((void**)&uB,    g_u);
    cudaGetSymbolAddress((void**)&cB,    g_c);

    cudaFuncSetAttribute(attn3_kernel, cudaFuncAttributeMaxDynamicSharedMemorySize, ATT_SMEM);

    cudaMemcpyAsync(out, act, (size_t)NC * sizeof(float), cudaMemcpyDeviceToDevice, 0);

    // ---- weight pre-conversion (cln/plsc folded) ----
    conv_w_kernel<<<dim3(1152,1,8),256>>>(qw, 0, WB+OFF_QW, 768, 768, (long)NC, 0);
    conv_w_kernel<<<dim3(1152,1,8),256>>>(kw, 0, WB+OFF_KW, 768, 768, (long)NC, 0);
    conv_w_kernel<<<dim3(1152,1,8),256>>>(vw, 0, WB+OFF_VW, 768, 768, (long)NC, 0);
    conv_w_kernel<<<dim3(1152,1,8),256>>>(gw, 0, WB+OFF_GW, 768, 768, (long)NC, 0);
    conv_w_kernel<<<dim3(1152,1,8),256>>>(ow, 0, WB+OFF_OW, 768, 768, (long)NC, 0);
    conv_w_kernel<<<dim3(4608,1,8),256>>>(t1, 0, WB+OFF_T1, 768, 3072, (long)CD*2*FD, 0);
    conv_w_kernel<<<dim3(2304,1,8),256>>>(t2, 0, WB+OFF_T2, 1536, 768, (long)FD*CD, 0);
    conv_w_kernel<<<dim3(576,1,8),256>>>(a_csw, a_cln, WB+OFF_ACSW, 384, 768, (long)CSD*CD, CSD);
    conv_w_kernel<<<dim3(576,1,8),256>>>(a_cbw, a_cln, WB+OFF_ACBW, 384, 768, (long)CSD*CD, CSD);
    conv_w_kernel<<<dim3(576,1,8),256>>>(a_azw, 0,     WB+OFF_AAZW, 384, 768, (long)CSD*CD, 0);
    conv_w_kernel<<<dim3(576,1,8),256>>>(f_csw, f_cln, WB+OFF_FCSW, 384, 768, (long)CSD*CD, CSD);
    conv_w_kernel<<<dim3(576,1,8),256>>>(f_cbw, f_cln, WB+OFF_FCBW, 384, 768, (long)CSD*CD, CSD);
    conv_w_kernel<<<dim3(576,1,8),256>>>(f_azw, 0,     WB+OFF_FAZW, 384, 768, (long)CSD*CD, 0);
    conv_pw_kernel<<<32,256>>>(pw, plsc, WB+OFF_PW);

    rowstats_kernel<<<(NT + 7) / 8, 256>>>(sc, scm, scr, NT, CSD);
    rowstats_kernel<<<(NN + 7) / 8, 256>>>(pc, pm, pr, NN, CPD);

    // pair logits -> fp16x2 transposed [l*16+h][q][k/2]
    gemm2(pc, WB+OFF_PW, pl, NN, 128, 128, pm, pr, 0, 0, 0, 0, 0, 2, 1, 0, 0, 0);

    // conditioning, batched across layers
    gemm2(sc, WB+OFF_ACSW, sA, NT, CD, CSD, scm, scr, 0, a_csb, 1, 0, 0, 0,
          LL, 147456, NC, CD);
    gemm2(sc, WB+OFF_ACBW, kA, NT, CD, CSD, scm, scr, 0, 0, 0, 0, 0, 0,
          LL, 147456, NC, 0);
    gemm2(sc, WB+OFF_AAZW, zA, NT, CD, CSD, 0, 0, 0, a_azb, 1, 0, 0, 0,
          LL, 147456, NC, CD);
    gemm2(sc, WB+OFF_FCSW, sF, NT, CD, CSD, scm, scr, 0, f_csb, 1, 0, 0, 0,
          LL, 147456, NC, CD);
    gemm2(sc, WB+OFF_FCBW, kF, NT, CD, CSD, scm, scr, 0, 0, 0, 0, 0, 0,
          LL, 147456, NC, 0);
    gemm2(sc, WB+OFF_FAZW, zF, NT, CD, CSD, 0, 0, 0, f_azb, 1, 0, 0, 0,
          LL, 147456, NC, CD);

    for(int l = 0; l < LL; l++){
        adaln_apply_kernel<<<NT, 256>>>(out, sA + (size_t)l*NC, kA + (size_t)l*NC, xb);

        // q,k,v,gate: z=0,1 bf16; z=2 bf16 transposed; z=3 gate f32 sigmoid
        gemm2(xb, WB + OFF_QW + (size_t)l*U_SQ, qkvg, NT, CD, CD, 0, 0, 0,
              qb + (size_t)l*CD, 0, 0, 0, 0,
              4, 2359296, NC, 0, gb + (size_t)l*CD, /*multi=*/1, QKV16);

        attn3_kernel<<<dim3(NT/32, HH), 256, ATT_SMEM>>>(
            QKV16, QKV16 + 294912, QKV16 + 2*294912,
            (const uint32_t*)pl + (size_t)l*16*294912, mask, atB);

        // a += sig_az_attn * ((attn*gate) @ out_w)
        gemm2(atB, WB + OFF_OW + (size_t)l*U_SQ, out, NT, CD, CD, 0, 0,
              qkvg + 3*NC, 0, 0, zA + (size_t)l*NC, 1, 0, 1, 0, 0, 0);

        adaln_apply_kernel<<<NT, 256>>>(out, sF + (size_t)l*NC, kF + (size_t)l*NC, xb);

        gemm2(xb, WB + OFF_T1 + (size_t)l*1179648, uB, NT, 2*FD, CD, 0, 0, 0,
              0, 0, 0, 0, 0, 1, 0, 0, 0);
        glu_kernel<<<(768*1536)/256, 256>>>(uB, cB);

        // a += sig_az_ffw * (c @ t2)
        gemm2(cB, WB + OFF_T2 + (size_t)l*589824, out, NT, CD, FD, 0, 0, 0,
              0, 0, zF + (size_t)l*NC, 1, 0, 1, 0, 0, 0);
    }
}